// round 2
// baseline (speedup 1.0000x reference)
#include <cuda_runtime.h>
#include <math.h>

// ---------------- problem constants ----------------
#define B_  2
#define L_  16
#define C_  64
#define S_  64
#define W_  128
#define R_  32
#define H_  32
#define BL_ (B_*L_)          // 32
#define SW_ (S_*W_)          // 8192
#define CR_ (C_*R_)          // 2048
#define PLANES_ (BL_*C_)     // 2048
#define NELEM_ (PLANES_*SW_) // 16777216

// ---------------- device scratch ----------------
__device__ float g_lam_re[CR_], g_lam_im[CR_], g_gamma[CR_];
__device__ float g_ctx[BL_*C_];
__device__ float g_mod_re[BL_*CR_], g_mod_im[BL_*CR_];
__device__ float g_u_re[BL_*CR_],  g_u_im[BL_*CR_];
__device__ float g_h_re[BL_*CR_],  g_h_im[BL_*CR_];
__device__ float g_P[C_*C_*9], g_Q[C_*C_*9];
__device__ float g_A[C_*C_*9], g_Bk[C_*C_*9];
__device__ float g_T[C_*9], g_c0[C_];
__device__ float g_yr[NELEM_];
__device__ float g_yi[NELEM_];
__device__ float g_fused[NELEM_];

// ---------------- helpers ----------------
__device__ __forceinline__ float blockReduceSum(float v, float* sbuf) {
    int lane = threadIdx.x & 31, warp = threadIdx.x >> 5;
    #pragma unroll
    for (int o = 16; o > 0; o >>= 1) v += __shfl_down_sync(0xffffffffu, v, o);
    if (lane == 0) sbuf[warp] = v;
    __syncthreads();
    int nw = blockDim.x >> 5;
    v = (threadIdx.x < nw) ? sbuf[threadIdx.x] : 0.f;
    if (warp == 0) {
        #pragma unroll
        for (int o = 16; o > 0; o >>= 1) v += __shfl_down_sync(0xffffffffu, v, o);
    }
    return v;  // valid in thread 0
}

// ---------------- K1: poles ----------------
__global__ void k_poles(const float* __restrict__ nu_log, const float* __restrict__ th_log,
                        const float* __restrict__ dnu, const float* __restrict__ dth) {
    int i = blockIdx.x * 256 + threadIdx.x;
    if (i >= CR_) return;
    float nu = expf(nu_log[i] + dnu[i]);
    float th = expf(th_log[i] + dth[i]);
    float el = expf(-nu);
    g_lam_re[i] = el * cosf(th);
    g_lam_im[i] = el * sinf(th);
    g_gamma[i]  = sqrtf(fmaxf(1.f - el * el, 1e-6f));
}

// ---------------- K7a: P,Q = fuse ∘ conv kernels, const bias ----------------
// grid 64 (o), block 576 (c*9+t)
__global__ void k_pq(const float* __restrict__ fuse_k, const float* __restrict__ convr_k,
                     const float* __restrict__ convi_k, const float* __restrict__ convr_b,
                     const float* __restrict__ convi_b, const float* __restrict__ fuse_b) {
    int o = blockIdx.x, tid = threadIdx.x;
    __shared__ float sF1[C_], sF2[C_];
    if (tid < 64)       sF1[tid]      = fuse_k[o*128 + tid];
    else if (tid < 128) sF2[tid - 64] = fuse_k[o*128 + tid];
    __syncthreads();
    float p = 0.f, q = 0.f;
    for (int m = 0; m < C_; m++) {
        p += sF1[m] * convr_k[m*576 + tid];
        q += sF2[m] * convi_k[m*576 + tid];
    }
    g_P[o*576 + tid] = p;
    g_Q[o*576 + tid] = q;
    if (tid == 0) {
        float v = fuse_b[o];
        for (int m = 0; m < C_; m++) v += sF1[m]*convr_b[m] + sF2[m]*convi_b[m];
        g_c0[o] = v;
    }
}

// ---------------- K7b: fold proj into combined kernels A,B and border taps T ----------------
// grid 64 (o), block 576 (c'*9+t)
__global__ void k_ab(const float* __restrict__ Wr, const float* __restrict__ Wi,
                     const float* __restrict__ br, const float* __restrict__ bi) {
    int o = blockIdx.x, tid = threadIdx.x;
    int cp = tid / 9, t = tid % 9;
    __shared__ float sP[576], sQ[576];
    sP[tid] = g_P[o*576 + tid];
    sQ[tid] = g_Q[o*576 + tid];
    __syncthreads();
    float a = 0.f, bb = 0.f;
    for (int cc = 0; cc < C_; cc++) {
        float p = sP[cc*9 + t], q = sQ[cc*9 + t];
        float wr = Wr[cc*C_ + cp], wi = Wi[cc*C_ + cp];
        a  += p * wr + q * wi;
        bb += -p * wi + q * wr;
    }
    g_A[o*576 + tid]  = a;
    g_Bk[o*576 + tid] = bb;
    if (tid < 9) {
        float tt = 0.f;
        for (int cc = 0; cc < C_; cc++)
            tt += sP[cc*9 + tid]*br[cc] + sQ[cc*9 + tid]*bi[cc];
        g_T[o*9 + tid] = tt;
    }
}

// ---------------- K2: spatial-mean context ----------------
// grid PLANES_ (b,l,c), block 256
__global__ void k_ctx(const float* __restrict__ x) {
    __shared__ float sbuf[8];
    int blc = blockIdx.x;
    const float* xp = x + (size_t)blc * SW_;
    float s = 0.f;
    for (int i = threadIdx.x; i < SW_; i += 256) s += xp[i];
    s = blockReduceSum(s, sbuf);
    if (threadIdx.x == 0) g_ctx[blc] = s * (1.f / (float)SW_);
}

// ---------------- K3: MLP -> modulation m = gamma*(1+forcing) ----------------
// grid BL_, block 256
__global__ void k_mlp(const float* __restrict__ w1, const float* __restrict__ b1,
                      const float* __restrict__ w2, const float* __restrict__ b2,
                      const float* __restrict__ fscale) {
    __shared__ float sc[C_], shid[H_], sf[CR_*2];
    int bl = blockIdx.x, tid = threadIdx.x;
    if (tid < C_) sc[tid] = g_ctx[bl*C_ + tid];
    __syncthreads();
    if (tid < H_) {
        float v = b1[tid];
        for (int cc = 0; cc < C_; cc++) v += sc[cc] * w1[cc*H_ + tid];
        shid[tid] = tanhf(v);
    }
    __syncthreads();
    for (int k = tid; k < CR_*2; k += 256) {
        float v = b2[k];
        #pragma unroll
        for (int j = 0; j < H_; j++) v += shid[j] * w2[j*(CR_*2) + k];
        sf[k] = v;
    }
    __syncthreads();
    float fs = *fscale;
    for (int cr = tid; cr < CR_; cr += 256) {
        float ga = g_gamma[cr];
        g_mod_re[bl*CR_ + cr] = ga * (1.f + fs * sf[2*cr]);
        g_mod_im[bl*CR_ + cr] = ga * (fs * sf[2*cr + 1]);
    }
}

// ---------------- K4: low-rank projection u = mod * (x · conj(U) · conj(V)) ----------------
// grid PLANES_, block 128 (one thread per w). dyn smem: x(8192) + U4(4096) + V4(8192) + red(256)
#define SMEM_U_BYTES ((8192 + 4096 + 8192 + 256) * 4)
__global__ void k_u(const float* __restrict__ x,
                    const float* __restrict__ Ur, const float* __restrict__ Ui,
                    const float* __restrict__ Vr, const float* __restrict__ Vi) {
    extern __shared__ float sm[];
    float* sx   = sm;
    float* sU   = sm + 8192;
    float* sV   = sm + 8192 + 4096;
    float* sred = sm + 8192 + 4096 + 8192;
    int tid = threadIdx.x;
    int blc = blockIdx.x;
    int c = blc % C_;
    const float* xp = x + (size_t)blc * SW_;
    for (int i = tid; i < SW_; i += 128) sx[i] = xp[i];
    for (int i = tid; i < S_*R_; i += 128) {
        int s = i >> 5, r = i & 31;
        int off = s*64 + (r >> 1)*4 + (r & 1)*2;
        sU[off]     = Ur[c*S_*R_ + i];
        sU[off + 1] = Ui[c*S_*R_ + i];
    }
    for (int i = tid; i < W_*R_; i += 128) {
        int w = i >> 5, r = i & 31;
        int off = w*64 + (r >> 1)*4 + (r & 1)*2;
        sV[off]     = Vr[c*W_*R_ + i];
        sV[off + 1] = Vi[c*W_*R_ + i];
    }
    __syncthreads();
    int w = tid, lane = tid & 31, warp = tid >> 5;
    const float4* u4base = reinterpret_cast<const float4*>(sU);
    const float4* v4base = reinterpret_cast<const float4*>(sV);
    for (int r2 = 0; r2 < 16; r2++) {
        float ar0 = 0, ai0 = 0, ar1 = 0, ai1 = 0;
        const float4* u4 = u4base + r2;
        #pragma unroll 8
        for (int s = 0; s < S_; s++) {
            float xv = sx[s*W_ + w];
            float4 u = u4[s*16];
            ar0 = fmaf(xv, u.x, ar0); ai0 = fmaf(xv, u.y, ai0);
            ar1 = fmaf(xv, u.z, ar1); ai1 = fmaf(xv, u.w, ai1);
        }
        float4 v = v4base[w*16 + r2];  // (Vr0,Vi0,Vr1,Vi1)
        float pr0 = ar0*v.x - ai0*v.y;
        float pi0 = -(ar0*v.y + ai0*v.x);
        float pr1 = ar1*v.z - ai1*v.w;
        float pi1 = -(ar1*v.w + ai1*v.z);
        #pragma unroll
        for (int o = 16; o > 0; o >>= 1) {
            pr0 += __shfl_down_sync(0xffffffffu, pr0, o);
            pi0 += __shfl_down_sync(0xffffffffu, pi0, o);
            pr1 += __shfl_down_sync(0xffffffffu, pr1, o);
            pi1 += __shfl_down_sync(0xffffffffu, pi1, o);
        }
        if (lane == 0) {
            int r = r2*2;
            sred[(warp*R_ + r)*2]     = pr0; sred[(warp*R_ + r)*2 + 1]     = pi0;
            sred[(warp*R_ + r + 1)*2] = pr1; sred[(warp*R_ + r + 1)*2 + 1] = pi1;
        }
    }
    __syncthreads();
    if (tid < R_) {
        int r = tid;
        float ur = 0, ui = 0;
        #pragma unroll
        for (int wp = 0; wp < 4; wp++) {
            ur += sred[(wp*R_ + r)*2];
            ui += sred[(wp*R_ + r)*2 + 1];
        }
        float mr = g_mod_re[blc*R_ + r], mi = g_mod_im[blc*R_ + r];
        g_u_re[blc*R_ + r] = mr*ur - mi*ui;
        g_u_im[blc*R_ + r] = mr*ui + mi*ur;
    }
}

// ---------------- K5: diagonal scan over L ----------------
// grid 16, block 256 -> 4096 threads = B*C*R
__global__ void k_scan() {
    int t = blockIdx.x * 256 + threadIdx.x;
    int b = t >> 11;        // / CR_
    int cr = t & (CR_ - 1);
    float lr = g_lam_re[cr], li = g_lam_im[cr];
    float hr = 0.f, hi = 0.f;
    #pragma unroll
    for (int l = 0; l < L_; l++) {
        int idx = (b*L_ + l)*CR_ + cr;
        float ur = g_u_re[idx], ui = g_u_im[idx];
        float nr = lr*hr - li*hi + ur;
        float ni = lr*hi + li*hr + ui;
        hr = nr; hi = ni;
        g_h_re[idx] = hr;
        g_h_im[idx] = hi;
    }
}

// ---------------- K6: reconstruct y = (h·U)·V ----------------
// grid PLANES_, block 512. dyn smem: U(4096) + Vpad(8448) + gpad(4224) + h(64)
#define SMEM_R_BYTES ((4096 + 8448 + 4224 + 64) * 4)
__global__ void k_recon(const float* __restrict__ Ur, const float* __restrict__ Ui,
                        const float* __restrict__ Vr, const float* __restrict__ Vi) {
    extern __shared__ float sm[];
    float* sU = sm;                       // [s*32+r] *2
    float* sV = sm + 4096;                // [(w*33+r)] *2
    float* sg = sm + 4096 + 8448;         // [(s*33+r)] *2
    float* sh = sm + 4096 + 8448 + 4224;  // [r] *2
    int tid = threadIdx.x;
    int blc = blockIdx.x;
    int c = blc % C_;
    if (tid < R_) {
        sh[tid*2]     = g_h_re[blc*R_ + tid];
        sh[tid*2 + 1] = g_h_im[blc*R_ + tid];
    }
    for (int i = tid; i < S_*R_; i += 512) {
        sU[i*2]     = Ur[c*S_*R_ + i];
        sU[i*2 + 1] = Ui[c*S_*R_ + i];
    }
    for (int i = tid; i < W_*R_; i += 512) {
        int w = i >> 5, r = i & 31;
        sV[(w*33 + r)*2]     = Vr[c*W_*R_ + i];
        sV[(w*33 + r)*2 + 1] = Vi[c*W_*R_ + i];
    }
    __syncthreads();
    for (int i = tid; i < S_*R_; i += 512) {
        int s = i >> 5, r = i & 31;
        float hr = sh[r*2], hi = sh[r*2 + 1];
        float ur = sU[i*2], ui = sU[i*2 + 1];
        sg[(s*33 + r)*2]     = hr*ur - hi*ui;
        sg[(s*33 + r)*2 + 1] = hr*ui + hi*ur;
    }
    __syncthreads();
    int s = tid >> 3, wg = tid & 7;
    float accr[16], acci[16];
    #pragma unroll
    for (int k = 0; k < 16; k++) { accr[k] = 0.f; acci[k] = 0.f; }
    const float2* g2 = reinterpret_cast<const float2*>(sg);
    const float2* v2 = reinterpret_cast<const float2*>(sV);
    #pragma unroll 2
    for (int r = 0; r < R_; r++) {
        float2 g = g2[s*33 + r];
        #pragma unroll
        for (int k = 0; k < 16; k++) {
            int w = wg + 8*k;
            float2 v = v2[w*33 + r];
            accr[k] = fmaf(g.x, v.x, fmaf(-g.y, v.y, accr[k]));
            acci[k] = fmaf(g.x, v.y, fmaf( g.y, v.x, acci[k]));
        }
    }
    float* pyr = g_yr + (size_t)blc*SW_ + s*W_ + wg;
    float* pyi = g_yi + (size_t)blc*SW_ + s*W_ + wg;
    #pragma unroll
    for (int k = 0; k < 16; k++) {
        pyr[8*k] = accr[k];
        pyi[8*k] = acci[k];
    }
}

// ---------------- K8: fused double 3x3 conv (proj+convs+fuse all folded) ----------------
// grid (BL_, 8 tiles, 8 o-tiles), block 256. 32x32 spatial tile, 8 out channels.
__global__ void __launch_bounds__(256) k_conv() {
    __shared__ float syr[34*36];
    __shared__ float syi[34*36];
    __shared__ float sA[8*9], sB[8*9], sT[8*9], sc0[8];
    int tid = threadIdx.x;
    int tx = tid & 31, ty = tid >> 5;
    int bl = blockIdx.x;
    int s0 = (blockIdx.y >> 2) * 32, w0 = (blockIdx.y & 3) * 32;
    int o0 = blockIdx.z * 8;
    if (tid < 72) sT[tid] = g_T[(o0 + tid/9)*9 + tid%9];
    if (tid < 8)  sc0[tid] = g_c0[o0 + tid];
    __syncthreads();
    float acc[4][8];
    int wglob = w0 + tx;
    #pragma unroll
    for (int p = 0; p < 4; p++) {
        int sglob = s0 + ty*4 + p;
        #pragma unroll
        for (int o = 0; o < 8; o++) acc[p][o] = sc0[o];
        #pragma unroll
        for (int dy = 0; dy < 3; dy++)
            #pragma unroll
            for (int dx = 0; dx < 3; dx++) {
                bool valid = ((unsigned)(sglob + dy - 1) < S_) && ((unsigned)(wglob + dx - 1) < W_);
                if (valid) {
                    #pragma unroll
                    for (int o = 0; o < 8; o++) acc[p][o] += sT[o*9 + dy*3 + dx];
                }
            }
    }
    const float* yrbase = g_yr + (size_t)bl * (C_*SW_);
    const float* yibase = g_yi + (size_t)bl * (C_*SW_);
    for (int ci = 0; ci < C_; ci++) {
        __syncthreads();
        for (int i = tid; i < 34*34; i += 256) {
            int row = i / 34, col = i % 34;
            int gs = s0 - 1 + row, gw = w0 - 1 + col;
            bool ok = ((unsigned)gs < S_) && ((unsigned)gw < W_);
            size_t gidx = (size_t)ci*SW_ + gs*W_ + gw;
            syr[row*36 + col] = ok ? yrbase[gidx] : 0.f;
            syi[row*36 + col] = ok ? yibase[gidx] : 0.f;
        }
        if (tid < 72) {
            sA[tid] = g_A [((o0 + tid/9)*C_ + ci)*9 + tid%9];
            sB[tid] = g_Bk[((o0 + tid/9)*C_ + ci)*9 + tid%9];
        }
        __syncthreads();
        #pragma unroll
        for (int t = 0; t < 9; t++) {
            int dy = t / 3, dx = t % 3;
            float a[8], b[8];
            #pragma unroll
            for (int o = 0; o < 8; o++) { a[o] = sA[o*9 + t]; b[o] = sB[o*9 + t]; }
            #pragma unroll
            for (int p = 0; p < 4; p++) {
                float xr = syr[(ty*4 + p + dy)*36 + tx + dx];
                float xi = syi[(ty*4 + p + dy)*36 + tx + dx];
                #pragma unroll
                for (int o = 0; o < 8; o++)
                    acc[p][o] = fmaf(a[o], xr, fmaf(b[o], xi, acc[p][o]));
            }
        }
    }
    float* outb = g_fused + (size_t)bl * (C_*SW_);
    #pragma unroll
    for (int p = 0; p < 4; p++) {
        int sglob = s0 + ty*4 + p;
        #pragma unroll
        for (int o = 0; o < 8; o++)
            outb[(size_t)(o0 + o)*SW_ + sglob*W_ + wglob] = acc[p][o];
    }
}

// ---------------- K9: LayerNorm over (S,W) + residual ----------------
// grid PLANES_, block 256
__global__ void k_ln(const float* __restrict__ x, const float* __restrict__ lng,
                     const float* __restrict__ lnb, float* __restrict__ out) {
    __shared__ float sbuf1[8], sbuf2[8];
    __shared__ float s_mu, s_rstd;
    int blc = blockIdx.x, tid = threadIdx.x;
    const float* fp = g_fused + (size_t)blc * SW_;
    float v[32];
    float sum = 0.f, sq = 0.f;
    #pragma unroll
    for (int k = 0; k < 32; k++) {
        float t = fp[tid + 256*k];
        v[k] = t; sum += t; sq += t*t;
    }
    float ts = blockReduceSum(sum, sbuf1);
    __syncthreads();
    float tq = blockReduceSum(sq, sbuf2);
    if (tid == 0) {
        float mu = ts * (1.f / (float)SW_);
        float var = tq * (1.f / (float)SW_) - mu*mu;
        s_mu = mu;
        s_rstd = rsqrtf(var + 1e-5f);
    }
    __syncthreads();
    float mu = s_mu, rstd = s_rstd;
    const float* xp = x + (size_t)blc * SW_;
    float* op = out + (size_t)blc * SW_;
    #pragma unroll
    for (int k = 0; k < 32; k++) {
        int i = tid + 256*k;
        op[i] = (v[k] - mu) * rstd * lng[i] + lnb[i] + xp[i];
    }
}

// ---------------- launch ----------------
extern "C" void kernel_launch(void* const* d_in, const int* in_sizes, int n_in,
                              void* d_out, int out_size) {
    const float* x         = (const float*)d_in[0];
    const float* nu_log    = (const float*)d_in[1];
    const float* theta_log = (const float*)d_in[2];
    const float* disp_nu   = (const float*)d_in[3];
    const float* disp_th   = (const float*)d_in[4];
    const float* mlp_w1    = (const float*)d_in[5];
    const float* mlp_b1    = (const float*)d_in[6];
    const float* mlp_w2    = (const float*)d_in[7];
    const float* mlp_b2    = (const float*)d_in[8];
    const float* fscale    = (const float*)d_in[9];
    const float* U_row_r   = (const float*)d_in[10];
    const float* U_row_i   = (const float*)d_in[11];
    const float* V_col_r   = (const float*)d_in[12];
    const float* V_col_i   = (const float*)d_in[13];
    const float* proj_W_r  = (const float*)d_in[14];
    const float* proj_W_i  = (const float*)d_in[15];
    const float* proj_b_r  = (const float*)d_in[16];
    const float* proj_b_i  = (const float*)d_in[17];
    const float* convr_k   = (const float*)d_in[18];
    const float* convr_b   = (const float*)d_in[19];
    const float* convi_k   = (const float*)d_in[20];
    const float* convi_b   = (const float*)d_in[21];
    const float* fuse_k    = (const float*)d_in[22];
    const float* fuse_b    = (const float*)d_in[23];
    const float* ln_g      = (const float*)d_in[24];
    const float* ln_b      = (const float*)d_in[25];
    float* out = (float*)d_out;

    cudaFuncSetAttribute(k_u,     cudaFuncAttributeMaxDynamicSharedMemorySize, SMEM_U_BYTES);
    cudaFuncSetAttribute(k_recon, cudaFuncAttributeMaxDynamicSharedMemorySize, SMEM_R_BYTES);

    k_poles<<<(CR_ + 255)/256, 256>>>(nu_log, theta_log, disp_nu, disp_th);
    k_pq<<<C_, 576>>>(fuse_k, convr_k, convi_k, convr_b, convi_b, fuse_b);
    k_ab<<<C_, 576>>>(proj_W_r, proj_W_i, proj_b_r, proj_b_i);
    k_ctx<<<PLANES_, 256>>>(x);
    k_mlp<<<BL_, 256>>>(mlp_w1, mlp_b1, mlp_w2, mlp_b2, fscale);
    k_u<<<PLANES_, 128, SMEM_U_BYTES>>>(x, U_row_r, U_row_i, V_col_r, V_col_i);
    k_scan<<<16, 256>>>();
    k_recon<<<PLANES_, 512, SMEM_R_BYTES>>>(U_row_r, U_row_i, V_col_r, V_col_i);
    k_conv<<<dim3(BL_, 8, 8), 256>>>();
    k_ln<<<PLANES_, 256>>>(x, ln_g, ln_b, out);
}

// round 4
// speedup vs baseline: 4.5838x; 4.5838x over previous
#include <cuda_runtime.h>
#include <cuda_fp16.h>
#include <math.h>
#include <stdint.h>

#define B_  2
#define L_  16
#define C_  64
#define S_  64
#define W_  128
#define R_  32
#define H_  32
#define BL_ (B_*L_)
#define SW_ (S_*W_)
#define CR_ (C_*R_)
#define PLANES_ (BL_*C_)
#define NELEM_ (PLANES_*SW_)

// ---------------- device scratch ----------------
__device__ float  g_lam_re[CR_], g_lam_im[CR_], g_gamma[CR_];
__device__ float  g_ctx[BL_*C_];
__device__ float  g_mod_re[BL_*CR_], g_mod_im[BL_*CR_];
__device__ float  g_u_re[BL_*CR_],  g_u_im[BL_*CR_];
__device__ float  g_h_re[BL_*CR_],  g_h_im[BL_*CR_];
__device__ float  g_P[C_*C_*9], g_Q[C_*C_*9];
__device__ float  g_A[C_*C_*9], g_Bk[C_*C_*9];
__device__ float  g_T[C_*9], g_c0[C_];
__device__ float2 g_y[NELEM_];
__device__ float  g_fused[NELEM_];
__device__ __half g_Bw[9*8192];     // per-tap swizzled [o=64][k=128] fp16 weights
__device__ float  g_bias[C_*SW_];   // bias + border-tap field

// ---------------- helpers ----------------
__device__ __forceinline__ float blockReduceSum(float v, float* sbuf) {
    int lane = threadIdx.x & 31, warp = threadIdx.x >> 5;
    #pragma unroll
    for (int o = 16; o > 0; o >>= 1) v += __shfl_down_sync(0xffffffffu, v, o);
    if (lane == 0) sbuf[warp] = v;
    __syncthreads();
    int nw = blockDim.x >> 5;
    v = (threadIdx.x < nw) ? sbuf[threadIdx.x] : 0.f;
    if (warp == 0) {
        #pragma unroll
        for (int o = 16; o > 0; o >>= 1) v += __shfl_down_sync(0xffffffffu, v, o);
    }
    return v;
}

// ---------------- K1: poles ----------------
__global__ void k_poles(const float* __restrict__ nu_log, const float* __restrict__ th_log,
                        const float* __restrict__ dnu, const float* __restrict__ dth) {
    int i = blockIdx.x * 256 + threadIdx.x;
    if (i >= CR_) return;
    float nu = expf(nu_log[i] + dnu[i]);
    float th = expf(th_log[i] + dth[i]);
    float el = expf(-nu);
    g_lam_re[i] = el * cosf(th);
    g_lam_im[i] = el * sinf(th);
    g_gamma[i]  = sqrtf(fmaxf(1.f - el * el, 1e-6f));
}

// ---------------- K7a: P,Q = fuse ∘ conv ----------------
__global__ void k_pq(const float* __restrict__ fuse_k, const float* __restrict__ convr_k,
                     const float* __restrict__ convi_k, const float* __restrict__ convr_b,
                     const float* __restrict__ convi_b, const float* __restrict__ fuse_b) {
    int o = blockIdx.x, tid = threadIdx.x;
    __shared__ float sF1[C_], sF2[C_];
    if (tid < 64)       sF1[tid]      = fuse_k[o*128 + tid];
    else if (tid < 128) sF2[tid - 64] = fuse_k[o*128 + tid];
    __syncthreads();
    float p = 0.f, q = 0.f;
    for (int m = 0; m < C_; m++) {
        p += sF1[m] * convr_k[m*576 + tid];
        q += sF2[m] * convi_k[m*576 + tid];
    }
    g_P[o*576 + tid] = p;
    g_Q[o*576 + tid] = q;
    if (tid == 0) {
        float v = fuse_b[o];
        for (int m = 0; m < C_; m++) v += sF1[m]*convr_b[m] + sF2[m]*convi_b[m];
        g_c0[o] = v;
    }
}

// ---------------- K7b: fold proj -> A,B + border taps ----------------
__global__ void k_ab(const float* __restrict__ Wr, const float* __restrict__ Wi,
                     const float* __restrict__ br, const float* __restrict__ bi) {
    int o = blockIdx.x, tid = threadIdx.x;
    int cp = tid / 9, t = tid % 9;
    __shared__ float sP[576], sQ[576];
    sP[tid] = g_P[o*576 + tid];
    sQ[tid] = g_Q[o*576 + tid];
    __syncthreads();
    float a = 0.f, bb = 0.f;
    for (int cc = 0; cc < C_; cc++) {
        float p = sP[cc*9 + t], q = sQ[cc*9 + t];
        float wr = Wr[cc*C_ + cp], wi = Wi[cc*C_ + cp];
        a  += p * wr + q * wi;
        bb += -p * wi + q * wr;
    }
    g_A[o*576 + tid]  = a;
    g_Bk[o*576 + tid] = bb;
    if (tid < 9) {
        float tt = 0.f;
        for (int cc = 0; cc < C_; cc++)
            tt += sP[cc*9 + tid]*br[cc] + sQ[cc*9 + tid]*bi[cc];
        g_T[o*9 + tid] = tt;
    }
}

// ---------------- K7c: pack weights per tap into swizzled [o][k] fp16 ----------------
// row o: 128 halfs = 16 chunks of 8 halfs; chunk c stored at c ^ (o & 7).
__global__ void k_bprep() {
    int t = blockIdx.x;
    for (int i = threadIdx.x; i < 64*128; i += 256) {
        int n = i >> 7, k = i & 127;
        int ci = k >> 1, reim = k & 1;
        float wv = reim ? g_Bk[n*576 + ci*9 + t] : g_A[n*576 + ci*9 + t];
        int chunk = k >> 3;
        g_Bw[t*8192 + n*128 + ((chunk ^ (n & 7)) << 3) + (k & 7)] = __float2half(wv);
    }
}

// ---------------- K7d: bias + border-tap field ----------------
__global__ void k_bias() {
    int o = blockIdx.x;
    float c0 = g_c0[o];
    float T[9];
    #pragma unroll
    for (int t = 0; t < 9; t++) T[t] = g_T[o*9 + t];
    for (int i = threadIdx.x; i < SW_; i += 256) {
        int s = i >> 7, w = i & 127;
        float b = c0;
        #pragma unroll
        for (int t = 0; t < 9; t++) {
            int ds = t/3 - 1, dw = t%3 - 1;
            if (((unsigned)(s + ds) < (unsigned)S_) && ((unsigned)(w + dw) < (unsigned)W_))
                b += T[t];
        }
        g_bias[o*SW_ + i] = b;
    }
}

// ---------------- K2: context ----------------
__global__ void k_ctx(const float* __restrict__ x) {
    __shared__ float sbuf[8];
    int blc = blockIdx.x;
    const float* xp = x + (size_t)blc * SW_;
    float s = 0.f;
    for (int i = threadIdx.x; i < SW_; i += 256) s += xp[i];
    s = blockReduceSum(s, sbuf);
    if (threadIdx.x == 0) g_ctx[blc] = s * (1.f / (float)SW_);
}

// ---------------- K3: MLP ----------------
__global__ void k_mlp(const float* __restrict__ w1, const float* __restrict__ b1,
                      const float* __restrict__ w2, const float* __restrict__ b2,
                      const float* __restrict__ fscale) {
    __shared__ float sc[C_], shid[H_], sf[CR_*2];
    int bl = blockIdx.x, tid = threadIdx.x;
    if (tid < C_) sc[tid] = g_ctx[bl*C_ + tid];
    __syncthreads();
    if (tid < H_) {
        float v = b1[tid];
        for (int cc = 0; cc < C_; cc++) v += sc[cc] * w1[cc*H_ + tid];
        shid[tid] = tanhf(v);
    }
    __syncthreads();
    for (int k = tid; k < CR_*2; k += 256) {
        float v = b2[k];
        #pragma unroll
        for (int j = 0; j < H_; j++) v += shid[j] * w2[j*(CR_*2) + k];
        sf[k] = v;
    }
    __syncthreads();
    float fs = *fscale;
    for (int cr = tid; cr < CR_; cr += 256) {
        float ga = g_gamma[cr];
        g_mod_re[bl*CR_ + cr] = ga * (1.f + fs * sf[2*cr]);
        g_mod_im[bl*CR_ + cr] = ga * (fs * sf[2*cr + 1]);
    }
}

// ---------------- K4: low-rank projection ----------------
#define SMEM_U_BYTES ((8192 + 4096 + 8192 + 256) * 4)
__global__ void k_u(const float* __restrict__ x,
                    const float* __restrict__ Ur, const float* __restrict__ Ui,
                    const float* __restrict__ Vr, const float* __restrict__ Vi) {
    extern __shared__ float sm[];
    float* sx   = sm;
    float* sU   = sm + 8192;
    float* sV   = sm + 8192 + 4096;
    float* sred = sm + 8192 + 4096 + 8192;
    int tid = threadIdx.x;
    int blc = blockIdx.x;
    int c = blc % C_;
    const float* xp = x + (size_t)blc * SW_;
    for (int i = tid; i < SW_; i += 128) sx[i] = xp[i];
    for (int i = tid; i < S_*R_; i += 128) {
        int s = i >> 5, r = i & 31;
        int off = s*64 + (r >> 1)*4 + (r & 1)*2;
        sU[off]     = Ur[c*S_*R_ + i];
        sU[off + 1] = Ui[c*S_*R_ + i];
    }
    for (int i = tid; i < W_*R_; i += 128) {
        int w = i >> 5, r = i & 31;
        int off = w*64 + (r >> 1)*4 + (r & 1)*2;
        sV[off]     = Vr[c*W_*R_ + i];
        sV[off + 1] = Vi[c*W_*R_ + i];
    }
    __syncthreads();
    int w = tid, lane = tid & 31, warp = tid >> 5;
    const float4* u4base = reinterpret_cast<const float4*>(sU);
    const float4* v4base = reinterpret_cast<const float4*>(sV);
    for (int r2 = 0; r2 < 16; r2++) {
        float ar0 = 0, ai0 = 0, ar1 = 0, ai1 = 0;
        const float4* u4 = u4base + r2;
        #pragma unroll 8
        for (int s = 0; s < S_; s++) {
            float xv = sx[s*W_ + w];
            float4 u = u4[s*16];
            ar0 = fmaf(xv, u.x, ar0); ai0 = fmaf(xv, u.y, ai0);
            ar1 = fmaf(xv, u.z, ar1); ai1 = fmaf(xv, u.w, ai1);
        }
        float4 v = v4base[w*16 + r2];
        float pr0 = ar0*v.x - ai0*v.y;
        float pi0 = -(ar0*v.y + ai0*v.x);
        float pr1 = ar1*v.z - ai1*v.w;
        float pi1 = -(ar1*v.w + ai1*v.z);
        #pragma unroll
        for (int o = 16; o > 0; o >>= 1) {
            pr0 += __shfl_down_sync(0xffffffffu, pr0, o);
            pi0 += __shfl_down_sync(0xffffffffu, pi0, o);
            pr1 += __shfl_down_sync(0xffffffffu, pr1, o);
            pi1 += __shfl_down_sync(0xffffffffu, pi1, o);
        }
        if (lane == 0) {
            int r = r2*2;
            sred[(warp*R_ + r)*2]     = pr0; sred[(warp*R_ + r)*2 + 1]     = pi0;
            sred[(warp*R_ + r + 1)*2] = pr1; sred[(warp*R_ + r + 1)*2 + 1] = pi1;
        }
    }
    __syncthreads();
    if (tid < R_) {
        int r = tid;
        float ur = 0, ui = 0;
        #pragma unroll
        for (int wp = 0; wp < 4; wp++) {
            ur += sred[(wp*R_ + r)*2];
            ui += sred[(wp*R_ + r)*2 + 1];
        }
        float mr = g_mod_re[blc*R_ + r], mi = g_mod_im[blc*R_ + r];
        g_u_re[blc*R_ + r] = mr*ur - mi*ui;
        g_u_im[blc*R_ + r] = mr*ui + mi*ur;
    }
}

// ---------------- K5: scan ----------------
__global__ void k_scan() {
    int t = blockIdx.x * 256 + threadIdx.x;
    int b = t >> 11;
    int cr = t & (CR_ - 1);
    float lr = g_lam_re[cr], li = g_lam_im[cr];
    float hr = 0.f, hi = 0.f;
    #pragma unroll
    for (int l = 0; l < L_; l++) {
        int idx = (b*L_ + l)*CR_ + cr;
        float ur = g_u_re[idx], ui = g_u_im[idx];
        float nr = lr*hr - li*hi + ur;
        float ni = lr*hi + li*hr + ui;
        hr = nr; hi = ni;
        g_h_re[idx] = hr;
        g_h_im[idx] = hi;
    }
}

// ---------------- K6: reconstruct (interleaved float2 out) ----------------
#define SMEM_R_BYTES ((4096 + 8448 + 4224 + 64) * 4)
__global__ void k_recon(const float* __restrict__ Ur, const float* __restrict__ Ui,
                        const float* __restrict__ Vr, const float* __restrict__ Vi) {
    extern __shared__ float sm[];
    float* sU = sm;
    float* sV = sm + 4096;
    float* sg = sm + 4096 + 8448;
    float* sh = sm + 4096 + 8448 + 4224;
    int tid = threadIdx.x;
    int blc = blockIdx.x;
    int c = blc % C_;
    if (tid < R_) {
        sh[tid*2]     = g_h_re[blc*R_ + tid];
        sh[tid*2 + 1] = g_h_im[blc*R_ + tid];
    }
    for (int i = tid; i < S_*R_; i += 512) {
        sU[i*2]     = Ur[c*S_*R_ + i];
        sU[i*2 + 1] = Ui[c*S_*R_ + i];
    }
    for (int i = tid; i < W_*R_; i += 512) {
        int w = i >> 5, r = i & 31;
        sV[(w*33 + r)*2]     = Vr[c*W_*R_ + i];
        sV[(w*33 + r)*2 + 1] = Vi[c*W_*R_ + i];
    }
    __syncthreads();
    for (int i = tid; i < S_*R_; i += 512) {
        int s = i >> 5, r = i & 31;
        float hr = sh[r*2], hi = sh[r*2 + 1];
        float ur = sU[i*2], ui = sU[i*2 + 1];
        sg[(s*33 + r)*2]     = hr*ur - hi*ui;
        sg[(s*33 + r)*2 + 1] = hr*ui + hi*ur;
    }
    __syncthreads();
    int s = tid >> 3, wg = tid & 7;
    float accr[16], acci[16];
    #pragma unroll
    for (int k = 0; k < 16; k++) { accr[k] = 0.f; acci[k] = 0.f; }
    const float2* g2 = reinterpret_cast<const float2*>(sg);
    const float2* v2 = reinterpret_cast<const float2*>(sV);
    #pragma unroll 2
    for (int r = 0; r < R_; r++) {
        float2 g = g2[s*33 + r];
        #pragma unroll
        for (int k = 0; k < 16; k++) {
            int w = wg + 8*k;
            float2 v = v2[w*33 + r];
            accr[k] = fmaf(g.x, v.x, fmaf(-g.y, v.y, accr[k]));
            acci[k] = fmaf(g.x, v.y, fmaf( g.y, v.x, acci[k]));
        }
    }
    float2* py = g_y + (size_t)blc*SW_ + s*W_ + wg;
    #pragma unroll
    for (int k = 0; k < 16; k++) py[8*k] = make_float2(accr[k], acci[k]);
}

// ---------------- K8: fp16 mma.sync conv-GEMM ----------------
// grid 2048 = bl*64+s; 256 threads = 8 warps, warp owns M-slice of 16 pixels.
// SMEM: staged A rows [3][130 pw][64 half2] swizzled (99840 B) + B tap tile (16384 B)
#define CONV_SMEM (99840 + 16384)
__global__ void __launch_bounds__(256) k_conv_mma() {
    extern __shared__ __align__(16) char smc[];
    char* sB = smc + 99840;
    int tid = threadIdx.x, lane = tid & 31, warp = tid >> 5;
    int bl = blockIdx.x >> 6, s = blockIdx.x & 63;

    // stage 3 padded image rows as half2 (re,im) with 16B-chunk XOR swizzle
    const float2* ybl = g_y + (size_t)bl * (C_*SW_);
    for (int i = tid; i < 3*130*64; i += 256) {
        int ds = i / (130*64), rem = i % (130*64);
        int pw = rem >> 6, ci = rem & 63;
        int sr = s + ds - 1, w = pw - 1;
        float2 v = make_float2(0.f, 0.f);
        if (((unsigned)sr < (unsigned)S_) && ((unsigned)w < (unsigned)W_))
            v = ybl[(size_t)ci*SW_ + sr*W_ + w];
        __half2 h = __float22half2_rn(v);
        int chunk = ci >> 2;
        int phys = ds*33280 + pw*256 + ((chunk ^ (pw & 7)) << 4) + (ci & 3)*4;
        *(uint32_t*)(smc + phys) = *(uint32_t*)&h;
    }

    float acc[8][4];
    #pragma unroll
    for (int nt = 0; nt < 8; nt++)
        #pragma unroll
        for (int j = 0; j < 4; j++) acc[nt][j] = 0.f;

    uint32_t sAu, sBu;
    asm("{ .reg .u64 t; cvta.to.shared.u64 t, %1; cvt.u32.u64 %0, t; }" : "=r"(sAu) : "l"(smc));
    asm("{ .reg .u64 t; cvta.to.shared.u64 t, %1; cvt.u32.u64 %0, t; }" : "=r"(sBu) : "l"(sB));
    int m = warp * 16;

    #pragma unroll 1
    for (int t = 0; t < 9; t++) {
        __syncthreads();
        {   // copy swizzled B tap tile (16 KB)
            const uint4* src = (const uint4*)(g_Bw + t*8192);
            uint4* dst = (uint4*)sB;
            #pragma unroll
            for (int i = 0; i < 4; i++) dst[tid + 256*i] = src[tid + 256*i];
        }
        __syncthreads();
        int tx = t % 3, ty = t / 3;
        #pragma unroll 1
        for (int ks = 0; ks < 8; ks++) {
            // A fragment: 16x16 via ldmatrix.x4
            int row = m + (lane & 15) + tx;
            int cblk = ks*2 + (lane >> 4);
            uint32_t aaddr = sAu + ty*33280 + row*256 + (uint32_t)((cblk ^ (row & 7)) << 4);
            uint32_t a0, a1, a2, a3;
            asm volatile("ldmatrix.sync.aligned.m8n8.x4.shared.b16 {%0,%1,%2,%3}, [%4];"
                         : "=r"(a0), "=r"(a1), "=r"(a2), "=r"(a3) : "r"(aaddr));
            #pragma unroll
            for (int nt = 0; nt < 8; nt++) {
                int n = nt*8 + (lane & 7);
                int cb = ks*2 + ((lane >> 3) & 1);
                uint32_t baddr = sBu + n*256 + (uint32_t)((cb ^ (n & 7)) << 4);
                uint32_t b0, b1;
                asm volatile("ldmatrix.sync.aligned.m8n8.x2.shared.b16 {%0,%1}, [%2];"
                             : "=r"(b0), "=r"(b1) : "r"(baddr));
                asm volatile("mma.sync.aligned.m16n8k16.row.col.f32.f16.f16.f32 "
                             "{%0,%1,%2,%3}, {%4,%5,%6,%7}, {%8,%9}, {%0,%1,%2,%3};"
                             : "+f"(acc[nt][0]), "+f"(acc[nt][1]), "+f"(acc[nt][2]), "+f"(acc[nt][3])
                             : "r"(a0), "r"(a1), "r"(a2), "r"(a3), "r"(b0), "r"(b1));
            }
        }
    }
    // store: fragment (m=g/g+8, n=2t/2t+1)
    int g = lane >> 2, tq = lane & 3;
    float* ob = g_fused + (size_t)bl * (C_*SW_) + s*W_ + m + g;
    #pragma unroll
    for (int nt = 0; nt < 8; nt++) {
        int o0 = nt*8 + 2*tq;
        ob[(size_t)o0*SW_]           = acc[nt][0];
        ob[(size_t)(o0 + 1)*SW_]     = acc[nt][1];
        ob[(size_t)o0*SW_ + 8]       = acc[nt][2];
        ob[(size_t)(o0 + 1)*SW_ + 8] = acc[nt][3];
    }
}

// ---------------- K9: LayerNorm (+ bias field) + residual ----------------
__global__ void k_ln(const float* __restrict__ x, const float* __restrict__ lng,
                     const float* __restrict__ lnb, float* __restrict__ out) {
    __shared__ float sbuf1[8], sbuf2[8];
    __shared__ float s_mu, s_rstd;
    int blc = blockIdx.x, tid = threadIdx.x;
    int o = blc % C_;
    const float* fp = g_fused + (size_t)blc * SW_;
    const float* bp = g_bias + (size_t)o * SW_;
    float v[32];
    float sum = 0.f, sq = 0.f;
    #pragma unroll
    for (int k = 0; k < 32; k++) {
        int i = tid + 256*k;
        float t = fp[i] + bp[i];
        v[k] = t; sum += t; sq += t*t;
    }
    float ts = blockReduceSum(sum, sbuf1);
    __syncthreads();
    float tq = blockReduceSum(sq, sbuf2);
    if (tid == 0) {
        float mu = ts * (1.f / (float)SW_);
        float var = tq * (1.f / (float)SW_) - mu*mu;
        s_mu = mu;
        s_rstd = rsqrtf(var + 1e-5f);
    }
    __syncthreads();
    float mu = s_mu, rstd = s_rstd;
    const float* xp = x + (size_t)blc * SW_;
    float* op = out + (size_t)blc * SW_;
    #pragma unroll
    for (int k = 0; k < 32; k++) {
        int i = tid + 256*k;
        op[i] = (v[k] - mu) * rstd * lng[i] + lnb[i] + xp[i];
    }
}

// ---------------- launch ----------------
extern "C" void kernel_launch(void* const* d_in, const int* in_sizes, int n_in,
                              void* d_out, int out_size) {
    const float* x         = (const float*)d_in[0];
    const float* nu_log    = (const float*)d_in[1];
    const float* theta_log = (const float*)d_in[2];
    const float* disp_nu   = (const float*)d_in[3];
    const float* disp_th   = (const float*)d_in[4];
    const float* mlp_w1    = (const float*)d_in[5];
    const float* mlp_b1    = (const float*)d_in[6];
    const float* mlp_w2    = (const float*)d_in[7];
    const float* mlp_b2    = (const float*)d_in[8];
    const float* fscale    = (const float*)d_in[9];
    const float* U_row_r   = (const float*)d_in[10];
    const float* U_row_i   = (const float*)d_in[11];
    const float* V_col_r   = (const float*)d_in[12];
    const float* V_col_i   = (const float*)d_in[13];
    const float* proj_W_r  = (const float*)d_in[14];
    const float* proj_W_i  = (const float*)d_in[15];
    const float* proj_b_r  = (const float*)d_in[16];
    const float* proj_b_i  = (const float*)d_in[17];
    const float* convr_k   = (const float*)d_in[18];
    const float* convr_b   = (const float*)d_in[19];
    const float* convi_k   = (const float*)d_in[20];
    const float* convi_b   = (const float*)d_in[21];
    const float* fuse_k    = (const float*)d_in[22];
    const float* fuse_b    = (const float*)d_in[23];
    const float* ln_g      = (const float*)d_in[24];
    const float* ln_b      = (const float*)d_in[25];
    float* out = (float*)d_out;

    cudaFuncSetAttribute(k_u,        cudaFuncAttributeMaxDynamicSharedMemorySize, SMEM_U_BYTES);
    cudaFuncSetAttribute(k_recon,    cudaFuncAttributeMaxDynamicSharedMemorySize, SMEM_R_BYTES);
    cudaFuncSetAttribute(k_conv_mma, cudaFuncAttributeMaxDynamicSharedMemorySize, CONV_SMEM);

    k_poles<<<(CR_ + 255)/256, 256>>>(nu_log, theta_log, disp_nu, disp_th);
    k_pq<<<C_, 576>>>(fuse_k, convr_k, convi_k, convr_b, convi_b, fuse_b);
    k_ab<<<C_, 576>>>(proj_W_r, proj_W_i, proj_b_r, proj_b_i);
    k_bprep<<<9, 256>>>();
    k_bias<<<C_, 256>>>();
    k_ctx<<<PLANES_, 256>>>(x);
    k_mlp<<<BL_, 256>>>(mlp_w1, mlp_b1, mlp_w2, mlp_b2, fscale);
    k_u<<<PLANES_, 128, SMEM_U_BYTES>>>(x, U_row_r, U_row_i, V_col_r, V_col_i);
    k_scan<<<16, 256>>>();
    k_recon<<<PLANES_, 512, SMEM_R_BYTES>>>(U_row_r, U_row_i, V_col_r, V_col_i);
    k_conv_mma<<<2048, 256, CONV_SMEM>>>();
    k_ln<<<PLANES_, 256>>>(x, ln_g, ln_b, out);
}

// round 5
// speedup vs baseline: 5.7830x; 1.2616x over previous
#include <cuda_runtime.h>
#include <cuda_fp16.h>
#include <math.h>
#include <stdint.h>

#define B_  2
#define L_  16
#define C_  64
#define S_  64
#define W_  128
#define R_  32
#define H_  32
#define BL_ (B_*L_)
#define SW_ (S_*W_)
#define CR_ (C_*R_)
#define PLANES_ (BL_*C_)
#define NELEM_ (PLANES_*SW_)

// ---------------- device scratch ----------------
__device__ float    g_lam_re[CR_], g_lam_im[CR_], g_gamma[CR_];
__device__ float    g_ctx[BL_*C_];
__device__ float    g_mod_re[BL_*CR_], g_mod_im[BL_*CR_];
__device__ float    g_u_re[BL_*CR_],  g_u_im[BL_*CR_];
__device__ float    g_h_re[BL_*CR_],  g_h_im[BL_*CR_];
__device__ float    g_P[C_*C_*9], g_Q[C_*C_*9];
__device__ float    g_A[C_*C_*9], g_Bk[C_*C_*9];
__device__ float    g_T[C_*9], g_c0[C_];
__device__ uint32_t g_yh[NELEM_];   // half2 (re,im) planes
__device__ float    g_fused[NELEM_];
__device__ __half   g_Bw[9*8192];   // per-tap swizzled [o=64][k=128] fp16 weights
__device__ float    g_bias[C_*SW_]; // bias + border-tap field

// ---------------- helpers ----------------
__device__ __forceinline__ float blockReduceSum(float v, float* sbuf) {
    int lane = threadIdx.x & 31, warp = threadIdx.x >> 5;
    #pragma unroll
    for (int o = 16; o > 0; o >>= 1) v += __shfl_down_sync(0xffffffffu, v, o);
    if (lane == 0) sbuf[warp] = v;
    __syncthreads();
    int nw = blockDim.x >> 5;
    v = (threadIdx.x < nw) ? sbuf[threadIdx.x] : 0.f;
    if (warp == 0) {
        #pragma unroll
        for (int o = 16; o > 0; o >>= 1) v += __shfl_down_sync(0xffffffffu, v, o);
    }
    return v;
}

// ---------------- K1: poles ----------------
__global__ void k_poles(const float* __restrict__ nu_log, const float* __restrict__ th_log,
                        const float* __restrict__ dnu, const float* __restrict__ dth) {
    int i = blockIdx.x * 256 + threadIdx.x;
    if (i >= CR_) return;
    float nu = expf(nu_log[i] + dnu[i]);
    float th = expf(th_log[i] + dth[i]);
    float el = expf(-nu);
    g_lam_re[i] = el * cosf(th);
    g_lam_im[i] = el * sinf(th);
    g_gamma[i]  = sqrtf(fmaxf(1.f - el * el, 1e-6f));
}

// ---------------- K7a: P,Q = fuse ∘ conv ----------------
__global__ void k_pq(const float* __restrict__ fuse_k, const float* __restrict__ convr_k,
                     const float* __restrict__ convi_k, const float* __restrict__ convr_b,
                     const float* __restrict__ convi_b, const float* __restrict__ fuse_b) {
    int o = blockIdx.x, tid = threadIdx.x;
    __shared__ float sF1[C_], sF2[C_];
    if (tid < 64)       sF1[tid]      = fuse_k[o*128 + tid];
    else if (tid < 128) sF2[tid - 64] = fuse_k[o*128 + tid];
    __syncthreads();
    float p = 0.f, q = 0.f;
    for (int m = 0; m < C_; m++) {
        p += sF1[m] * convr_k[m*576 + tid];
        q += sF2[m] * convi_k[m*576 + tid];
    }
    g_P[o*576 + tid] = p;
    g_Q[o*576 + tid] = q;
    if (tid == 0) {
        float v = fuse_b[o];
        for (int m = 0; m < C_; m++) v += sF1[m]*convr_b[m] + sF2[m]*convi_b[m];
        g_c0[o] = v;
    }
}

// ---------------- K7b: fold proj -> A,B + border taps ----------------
__global__ void k_ab(const float* __restrict__ Wr, const float* __restrict__ Wi,
                     const float* __restrict__ br, const float* __restrict__ bi) {
    int o = blockIdx.x, tid = threadIdx.x;
    int cp = tid / 9, t = tid % 9;
    __shared__ float sP[576], sQ[576];
    sP[tid] = g_P[o*576 + tid];
    sQ[tid] = g_Q[o*576 + tid];
    __syncthreads();
    float a = 0.f, bb = 0.f;
    for (int cc = 0; cc < C_; cc++) {
        float p = sP[cc*9 + t], q = sQ[cc*9 + t];
        float wr = Wr[cc*C_ + cp], wi = Wi[cc*C_ + cp];
        a  += p * wr + q * wi;
        bb += -p * wi + q * wr;
    }
    g_A[o*576 + tid]  = a;
    g_Bk[o*576 + tid] = bb;
    if (tid < 9) {
        float tt = 0.f;
        for (int cc = 0; cc < C_; cc++)
            tt += sP[cc*9 + tid]*br[cc] + sQ[cc*9 + tid]*bi[cc];
        g_T[o*9 + tid] = tt;
    }
}

// ---------------- K7c: pack weights per tap into swizzled [o][k] fp16 ----------------
__global__ void k_bprep() {
    int t = blockIdx.x >> 3;
    int base = (blockIdx.x & 7) * 1024;
    for (int j = threadIdx.x; j < 1024; j += 256) {
        int i = base + j;
        int n = i >> 7, k = i & 127;
        int ci = k >> 1, reim = k & 1;
        float wv = reim ? g_Bk[n*576 + ci*9 + t] : g_A[n*576 + ci*9 + t];
        int chunk = k >> 3;
        g_Bw[t*8192 + n*128 + ((chunk ^ (n & 7)) << 3) + (k & 7)] = __float2half(wv);
    }
}

// ---------------- K7d: bias + border-tap field ----------------
__global__ void k_bias() {
    int o = blockIdx.x;
    float c0 = g_c0[o];
    float T[9];
    #pragma unroll
    for (int t = 0; t < 9; t++) T[t] = g_T[o*9 + t];
    for (int i = threadIdx.x; i < SW_; i += 256) {
        int s = i >> 7, w = i & 127;
        float b = c0;
        #pragma unroll
        for (int t = 0; t < 9; t++) {
            int ds = t/3 - 1, dw = t%3 - 1;
            if (((unsigned)(s + ds) < (unsigned)S_) && ((unsigned)(w + dw) < (unsigned)W_))
                b += T[t];
        }
        g_bias[o*SW_ + i] = b;
    }
}

// ---------------- K3: MLP (needs g_ctx from k_u) ----------------
__global__ void k_mlp(const float* __restrict__ w1, const float* __restrict__ b1,
                      const float* __restrict__ w2, const float* __restrict__ b2,
                      const float* __restrict__ fscale) {
    __shared__ float sc[C_], shid[H_], sf[CR_*2];
    int bl = blockIdx.x, tid = threadIdx.x;
    if (tid < C_) sc[tid] = g_ctx[bl*C_ + tid];
    __syncthreads();
    if (tid < H_) {
        float v = b1[tid];
        for (int cc = 0; cc < C_; cc++) v += sc[cc] * w1[cc*H_ + tid];
        shid[tid] = tanhf(v);
    }
    __syncthreads();
    for (int k = tid; k < CR_*2; k += 256) {
        float v = b2[k];
        #pragma unroll
        for (int j = 0; j < H_; j++) v += shid[j] * w2[j*(CR_*2) + k];
        sf[k] = v;
    }
    __syncthreads();
    float fs = *fscale;
    for (int cr = tid; cr < CR_; cr += 256) {
        float ga = g_gamma[cr];
        g_mod_re[bl*CR_ + cr] = ga * (1.f + fs * sf[2*cr]);
        g_mod_im[bl*CR_ + cr] = ga * (fs * sf[2*cr + 1]);
    }
}

// ---------------- K4: low-rank projection (raw u) + ctx ----------------
#define SMEM_U_BYTES ((8192 + 4096 + 8192 + 256) * 4)
__global__ void k_u(const float* __restrict__ x,
                    const float* __restrict__ Ur, const float* __restrict__ Ui,
                    const float* __restrict__ Vr, const float* __restrict__ Vi) {
    extern __shared__ float sm[];
    float* sx   = sm;
    float* sU   = sm + 8192;
    float* sV   = sm + 8192 + 4096;
    float* sred = sm + 8192 + 4096 + 8192;
    int tid = threadIdx.x;
    int blc = blockIdx.x;
    int c = blc % C_;
    const float* xp = x + (size_t)blc * SW_;
    float csum = 0.f;
    for (int i = tid; i < SW_; i += 128) {
        float xv = xp[i];
        sx[i] = xv;
        csum += xv;
    }
    for (int i = tid; i < S_*R_; i += 128) {
        int s = i >> 5, r = i & 31;
        int off = s*64 + (r >> 1)*4 + (r & 1)*2;
        sU[off]     = Ur[c*S_*R_ + i];
        sU[off + 1] = Ui[c*S_*R_ + i];
    }
    for (int i = tid; i < W_*R_; i += 128) {
        int w = i >> 5, r = i & 31;
        int off = w*64 + (r >> 1)*4 + (r & 1)*2;
        sV[off]     = Vr[c*W_*R_ + i];
        sV[off + 1] = Vi[c*W_*R_ + i];
    }
    csum = blockReduceSum(csum, sred);
    if (tid == 0) g_ctx[blc] = csum * (1.f / (float)SW_);
    __syncthreads();
    int w = tid, lane = tid & 31, warp = tid >> 5;
    const float4* u4base = reinterpret_cast<const float4*>(sU);
    const float4* v4base = reinterpret_cast<const float4*>(sV);
    for (int r2 = 0; r2 < 16; r2++) {
        float ar0 = 0, ai0 = 0, ar1 = 0, ai1 = 0;
        const float4* u4 = u4base + r2;
        #pragma unroll 8
        for (int s = 0; s < S_; s++) {
            float xv = sx[s*W_ + w];
            float4 u = u4[s*16];
            ar0 = fmaf(xv, u.x, ar0); ai0 = fmaf(xv, u.y, ai0);
            ar1 = fmaf(xv, u.z, ar1); ai1 = fmaf(xv, u.w, ai1);
        }
        float4 v = v4base[w*16 + r2];
        float pr0 = ar0*v.x - ai0*v.y;
        float pi0 = -(ar0*v.y + ai0*v.x);
        float pr1 = ar1*v.z - ai1*v.w;
        float pi1 = -(ar1*v.w + ai1*v.z);
        #pragma unroll
        for (int o = 16; o > 0; o >>= 1) {
            pr0 += __shfl_down_sync(0xffffffffu, pr0, o);
            pi0 += __shfl_down_sync(0xffffffffu, pi0, o);
            pr1 += __shfl_down_sync(0xffffffffu, pr1, o);
            pi1 += __shfl_down_sync(0xffffffffu, pi1, o);
        }
        if (lane == 0) {
            int r = r2*2;
            sred[(warp*R_ + r)*2]     = pr0; sred[(warp*R_ + r)*2 + 1]     = pi0;
            sred[(warp*R_ + r + 1)*2] = pr1; sred[(warp*R_ + r + 1)*2 + 1] = pi1;
        }
    }
    __syncthreads();
    if (tid < R_) {
        int r = tid;
        float ur = 0, ui = 0;
        #pragma unroll
        for (int wp = 0; wp < 4; wp++) {
            ur += sred[(wp*R_ + r)*2];
            ui += sred[(wp*R_ + r)*2 + 1];
        }
        g_u_re[blc*R_ + r] = ur;
        g_u_im[blc*R_ + r] = ui;
    }
}

// ---------------- K5: scan (applies modulation) ----------------
__global__ void k_scan() {
    int t = blockIdx.x * 256 + threadIdx.x;
    int b = t >> 11;
    int cr = t & (CR_ - 1);
    float lr = g_lam_re[cr], li = g_lam_im[cr];
    float hr = 0.f, hi = 0.f;
    #pragma unroll
    for (int l = 0; l < L_; l++) {
        int idx = (b*L_ + l)*CR_ + cr;
        float ur_raw = g_u_re[idx], ui_raw = g_u_im[idx];
        float mr = g_mod_re[idx], mi = g_mod_im[idx];
        float ur = mr*ur_raw - mi*ui_raw;
        float ui = mr*ui_raw + mi*ur_raw;
        float nr = lr*hr - li*hi + ur;
        float ni = lr*hi + li*hr + ui;
        hr = nr; hi = ni;
        g_h_re[idx] = hr;
        g_h_im[idx] = hi;
    }
}

// ---------------- K6: reconstruct -> half2 planes ----------------
#define SMEM_R_BYTES ((4096 + 8448 + 4224 + 64) * 4)
__global__ void k_recon(const float* __restrict__ Ur, const float* __restrict__ Ui,
                        const float* __restrict__ Vr, const float* __restrict__ Vi) {
    extern __shared__ float sm[];
    float* sU = sm;
    float* sV = sm + 4096;
    float* sg = sm + 4096 + 8448;
    float* sh = sm + 4096 + 8448 + 4224;
    int tid = threadIdx.x;
    int blc = blockIdx.x;
    int c = blc % C_;
    if (tid < R_) {
        sh[tid*2]     = g_h_re[blc*R_ + tid];
        sh[tid*2 + 1] = g_h_im[blc*R_ + tid];
    }
    for (int i = tid; i < S_*R_; i += 512) {
        sU[i*2]     = Ur[c*S_*R_ + i];
        sU[i*2 + 1] = Ui[c*S_*R_ + i];
    }
    for (int i = tid; i < W_*R_; i += 512) {
        int w = i >> 5, r = i & 31;
        sV[(w*33 + r)*2]     = Vr[c*W_*R_ + i];
        sV[(w*33 + r)*2 + 1] = Vi[c*W_*R_ + i];
    }
    __syncthreads();
    for (int i = tid; i < S_*R_; i += 512) {
        int s = i >> 5, r = i & 31;
        float hr = sh[r*2], hi = sh[r*2 + 1];
        float ur = sU[i*2], ui = sU[i*2 + 1];
        sg[(s*33 + r)*2]     = hr*ur - hi*ui;
        sg[(s*33 + r)*2 + 1] = hr*ui + hi*ur;
    }
    __syncthreads();
    int s = tid >> 3, wg = tid & 7;
    float accr[16], acci[16];
    #pragma unroll
    for (int k = 0; k < 16; k++) { accr[k] = 0.f; acci[k] = 0.f; }
    const float2* g2 = reinterpret_cast<const float2*>(sg);
    const float2* v2 = reinterpret_cast<const float2*>(sV);
    #pragma unroll 2
    for (int r = 0; r < R_; r++) {
        float2 g = g2[s*33 + r];
        #pragma unroll
        for (int k = 0; k < 16; k++) {
            int w = wg + 8*k;
            float2 v = v2[w*33 + r];
            accr[k] = fmaf(g.x, v.x, fmaf(-g.y, v.y, accr[k]));
            acci[k] = fmaf(g.x, v.y, fmaf( g.y, v.x, acci[k]));
        }
    }
    uint32_t* py = g_yh + (size_t)blc*SW_ + s*W_ + wg;
    #pragma unroll
    for (int k = 0; k < 16; k++) {
        __half2 h = __floats2half2_rn(accr[k], acci[k]);
        py[8*k] = *(uint32_t*)&h;
    }
}

// ---------------- K8: fp16 mma.sync conv-GEMM, 2 s-rows per CTA ----------------
// grid 1024 = bl*32 + spair; 512 threads = 16 warps, one m16 tile each (M=256).
// SMEM: staged rows [4][130][64] half2 swizzled (133120 B) + B tap tile (16384 B)
#define CONV_SMEM (133120 + 16384)
__global__ void __launch_bounds__(512) k_conv_mma() {
    extern __shared__ __align__(16) char smc[];
    char* sB = smc + 133120;
    int tid = threadIdx.x, lane = tid & 31, warp = tid >> 5;
    int bl = blockIdx.x >> 5, s0 = (blockIdx.x & 31) * 2;

    // stage 4 padded rows (s0-1 .. s0+2), coalesced over w
    const uint32_t* ybl = g_yh + (size_t)bl * (C_*SW_);
    for (int i = tid; i < 4*130*64; i += 512) {
        int ci = i / 520, rem = i % 520;
        int ds = rem / 130, pw = rem % 130;
        int sr = s0 + ds - 1, w = pw - 1;
        uint32_t v = 0u;
        if (((unsigned)sr < (unsigned)S_) && ((unsigned)w < (unsigned)W_))
            v = ybl[(size_t)ci*SW_ + sr*W_ + w];
        int phys = ds*33280 + pw*256 + ((((ci >> 2) ^ (pw & 7))) << 4) + (ci & 3)*4;
        *(uint32_t*)(smc + phys) = v;
    }

    float acc[8][4];
    #pragma unroll
    for (int nt = 0; nt < 8; nt++)
        #pragma unroll
        for (int j = 0; j < 4; j++) acc[nt][j] = 0.f;

    uint32_t sAu, sBu;
    asm("{ .reg .u64 t; cvta.to.shared.u64 t, %1; cvt.u32.u64 %0, t; }" : "=r"(sAu) : "l"(smc));
    asm("{ .reg .u64 t; cvta.to.shared.u64 t, %1; cvt.u32.u64 %0, t; }" : "=r"(sBu) : "l"(sB));
    int s_row = warp >> 3;
    int wbase = (warp & 7) * 16;

    #pragma unroll 1
    for (int t = 0; t < 9; t++) {
        __syncthreads();
        {   // copy swizzled B tap tile (16 KB)
            const uint4* src = (const uint4*)(g_Bw + t*8192);
            uint4* dst = (uint4*)sB;
            dst[tid]       = src[tid];
            dst[tid + 512] = src[tid + 512];
        }
        __syncthreads();
        int tx = t % 3, ds = s_row + t / 3;
        #pragma unroll 1
        for (int ks = 0; ks < 8; ks++) {
            int row = wbase + (lane & 15) + tx;
            int cblk = ks*2 + (lane >> 4);
            uint32_t aaddr = sAu + ds*33280 + row*256 + (uint32_t)((cblk ^ (row & 7)) << 4);
            uint32_t a0, a1, a2, a3;
            asm volatile("ldmatrix.sync.aligned.m8n8.x4.shared.b16 {%0,%1,%2,%3}, [%4];"
                         : "=r"(a0), "=r"(a1), "=r"(a2), "=r"(a3) : "r"(aaddr));
            #pragma unroll
            for (int nt = 0; nt < 8; nt++) {
                int n = nt*8 + (lane & 7);
                int cb = ks*2 + ((lane >> 3) & 1);
                uint32_t baddr = sBu + n*256 + (uint32_t)((cb ^ (n & 7)) << 4);
                uint32_t b0, b1;
                asm volatile("ldmatrix.sync.aligned.m8n8.x2.shared.b16 {%0,%1}, [%2];"
                             : "=r"(b0), "=r"(b1) : "r"(baddr));
                asm volatile("mma.sync.aligned.m16n8k16.row.col.f32.f16.f16.f32 "
                             "{%0,%1,%2,%3}, {%4,%5,%6,%7}, {%8,%9}, {%0,%1,%2,%3};"
                             : "+f"(acc[nt][0]), "+f"(acc[nt][1]), "+f"(acc[nt][2]), "+f"(acc[nt][3])
                             : "r"(a0), "r"(a1), "r"(a2), "r"(a3), "r"(b0), "r"(b1));
            }
        }
    }
    // store fragments
    int g = lane >> 2, tq = lane & 3;
    float* ob = g_fused + (size_t)bl * (C_*SW_) + (s0 + s_row)*W_ + wbase + g;
    #pragma unroll
    for (int nt = 0; nt < 8; nt++) {
        int o0 = nt*8 + 2*tq;
        ob[(size_t)o0*SW_]           = acc[nt][0];
        ob[(size_t)(o0 + 1)*SW_]     = acc[nt][1];
        ob[(size_t)o0*SW_ + 8]       = acc[nt][2];
        ob[(size_t)(o0 + 1)*SW_ + 8] = acc[nt][3];
    }
}

// ---------------- K9: LayerNorm (+ bias field) + residual ----------------
__global__ void k_ln(const float* __restrict__ x, const float* __restrict__ lng,
                     const float* __restrict__ lnb, float* __restrict__ out) {
    __shared__ float sbuf1[8], sbuf2[8];
    __shared__ float s_mu, s_rstd;
    int blc = blockIdx.x, tid = threadIdx.x;
    int o = blc % C_;
    const float* fp = g_fused + (size_t)blc * SW_;
    const float* bp = g_bias + (size_t)o * SW_;
    float v[32];
    float sum = 0.f, sq = 0.f;
    #pragma unroll
    for (int k = 0; k < 32; k++) {
        int i = tid + 256*k;
        float t = fp[i] + bp[i];
        v[k] = t; sum += t; sq += t*t;
    }
    float ts = blockReduceSum(sum, sbuf1);
    __syncthreads();
    float tq = blockReduceSum(sq, sbuf2);
    if (tid == 0) {
        float mu = ts * (1.f / (float)SW_);
        float var = tq * (1.f / (float)SW_) - mu*mu;
        s_mu = mu;
        s_rstd = rsqrtf(var + 1e-5f);
    }
    __syncthreads();
    float mu = s_mu, rstd = s_rstd;
    const float* xp = x + (size_t)blc * SW_;
    float* op = out + (size_t)blc * SW_;
    #pragma unroll
    for (int k = 0; k < 32; k++) {
        int i = tid + 256*k;
        op[i] = (v[k] - mu) * rstd * lng[i] + lnb[i] + xp[i];
    }
}

// ---------------- launch ----------------
extern "C" void kernel_launch(void* const* d_in, const int* in_sizes, int n_in,
                              void* d_out, int out_size) {
    const float* x         = (const float*)d_in[0];
    const float* nu_log    = (const float*)d_in[1];
    const float* theta_log = (const float*)d_in[2];
    const float* disp_nu   = (const float*)d_in[3];
    const float* disp_th   = (const float*)d_in[4];
    const float* mlp_w1    = (const float*)d_in[5];
    const float* mlp_b1    = (const float*)d_in[6];
    const float* mlp_w2    = (const float*)d_in[7];
    const float* mlp_b2    = (const float*)d_in[8];
    const float* fscale    = (const float*)d_in[9];
    const float* U_row_r   = (const float*)d_in[10];
    const float* U_row_i   = (const float*)d_in[11];
    const float* V_col_r   = (const float*)d_in[12];
    const float* V_col_i   = (const float*)d_in[13];
    const float* proj_W_r  = (const float*)d_in[14];
    const float* proj_W_i  = (const float*)d_in[15];
    const float* proj_b_r  = (const float*)d_in[16];
    const float* proj_b_i  = (const float*)d_in[17];
    const float* convr_k   = (const float*)d_in[18];
    const float* convr_b   = (const float*)d_in[19];
    const float* convi_k   = (const float*)d_in[20];
    const float* convi_b   = (const float*)d_in[21];
    const float* fuse_k    = (const float*)d_in[22];
    const float* fuse_b    = (const float*)d_in[23];
    const float* ln_g      = (const float*)d_in[24];
    const float* ln_b      = (const float*)d_in[25];
    float* out = (float*)d_out;

    cudaFuncSetAttribute(k_u,        cudaFuncAttributeMaxDynamicSharedMemorySize, SMEM_U_BYTES);
    cudaFuncSetAttribute(k_recon,    cudaFuncAttributeMaxDynamicSharedMemorySize, SMEM_R_BYTES);
    cudaFuncSetAttribute(k_conv_mma, cudaFuncAttributeMaxDynamicSharedMemorySize, CONV_SMEM);

    k_poles<<<(CR_ + 255)/256, 256>>>(nu_log, theta_log, disp_nu, disp_th);
    k_pq<<<C_, 576>>>(fuse_k, convr_k, convi_k, convr_b, convi_b, fuse_b);
    k_ab<<<C_, 576>>>(proj_W_r, proj_W_i, proj_b_r, proj_b_i);
    k_bprep<<<72, 256>>>();
    k_bias<<<C_, 256>>>();
    k_u<<<PLANES_, 128, SMEM_U_BYTES>>>(x, U_row_r, U_row_i, V_col_r, V_col_i);
    k_mlp<<<BL_, 256>>>(mlp_w1, mlp_b1, mlp_w2, mlp_b2, fscale);
    k_scan<<<16, 256>>>();
    k_recon<<<PLANES_, 512, SMEM_R_BYTES>>>(U_row_r, U_row_i, V_col_r, V_col_i);
    k_conv_mma<<<1024, 512, CONV_SMEM>>>();
    k_ln<<<PLANES_, 256>>>(x, ln_g, ln_b, out);
}

// round 7
// speedup vs baseline: 7.6034x; 1.3148x over previous
#include <cuda_runtime.h>
#include <cuda_fp16.h>
#include <math.h>
#include <stdint.h>

#define B_  2
#define L_  16
#define C_  64
#define S_  64
#define W_  128
#define R_  32
#define H_  32
#define BL_ (B_*L_)
#define SW_ (S_*W_)
#define CR_ (C_*R_)
#define PLANES_ (BL_*C_)
#define NELEM_ (PLANES_*SW_)

// ---------------- device scratch ----------------
__device__ float    g_lam_re[CR_], g_lam_im[CR_], g_gamma[CR_];
__device__ float    g_ctx[BL_*C_];
__device__ float    g_mod_re[BL_*CR_], g_mod_im[BL_*CR_];
__device__ float    g_u_re[BL_*CR_],  g_u_im[BL_*CR_];
__device__ float    g_h_re[BL_*CR_],  g_h_im[BL_*CR_];
__device__ float    g_P[C_*C_*9], g_Q[C_*C_*9];
__device__ float    g_A[C_*C_*9], g_Bk[C_*C_*9];
__device__ float    g_T[C_*9], g_c0[C_];
__device__ uint32_t g_yh[NELEM_];   // half2 (re,im) planes
__device__ float    g_fused[NELEM_];
__device__ __half   g_Bw[9*8192];   // per-tap swizzled [o=64][k=128] fp16 weights
__device__ float    g_bias[C_*SW_]; // bias + border-tap field

// ---------------- helpers ----------------
__device__ __forceinline__ float blockReduceSum(float v, float* sbuf) {
    int lane = threadIdx.x & 31, warp = threadIdx.x >> 5;
    #pragma unroll
    for (int o = 16; o > 0; o >>= 1) v += __shfl_down_sync(0xffffffffu, v, o);
    if (lane == 0) sbuf[warp] = v;
    __syncthreads();
    int nw = blockDim.x >> 5;
    v = (threadIdx.x < nw) ? sbuf[threadIdx.x] : 0.f;
    if (warp == 0) {
        #pragma unroll
        for (int o = 16; o > 0; o >>= 1) v += __shfl_down_sync(0xffffffffu, v, o);
    }
    return v;
}
__device__ __forceinline__ uint32_t smem_u32(const void* p) {
    uint32_t a;
    asm("{ .reg .u64 t; cvta.to.shared.u64 t, %1; cvt.u32.u64 %0, t; }" : "=r"(a) : "l"(p));
    return a;
}

// ---------------- K1: poles ----------------
__global__ void k_poles(const float* __restrict__ nu_log, const float* __restrict__ th_log,
                        const float* __restrict__ dnu, const float* __restrict__ dth) {
    int i = blockIdx.x * 256 + threadIdx.x;
    if (i >= CR_) return;
    float nu = expf(nu_log[i] + dnu[i]);
    float th = expf(th_log[i] + dth[i]);
    float el = expf(-nu);
    g_lam_re[i] = el * cosf(th);
    g_lam_im[i] = el * sinf(th);
    g_gamma[i]  = sqrtf(fmaxf(1.f - el * el, 1e-6f));
}

// ---------------- K7a: P,Q = fuse ∘ conv ----------------
__global__ void k_pq(const float* __restrict__ fuse_k, const float* __restrict__ convr_k,
                     const float* __restrict__ convi_k, const float* __restrict__ convr_b,
                     const float* __restrict__ convi_b, const float* __restrict__ fuse_b) {
    int o = blockIdx.x, tid = threadIdx.x;
    __shared__ float sF1[C_], sF2[C_];
    if (tid < 64)       sF1[tid]      = fuse_k[o*128 + tid];
    else if (tid < 128) sF2[tid - 64] = fuse_k[o*128 + tid];
    __syncthreads();
    float p = 0.f, q = 0.f;
    for (int m = 0; m < C_; m++) {
        p += sF1[m] * convr_k[m*576 + tid];
        q += sF2[m] * convi_k[m*576 + tid];
    }
    g_P[o*576 + tid] = p;
    g_Q[o*576 + tid] = q;
    if (tid == 0) {
        float v = fuse_b[o];
        for (int m = 0; m < C_; m++) v += sF1[m]*convr_b[m] + sF2[m]*convi_b[m];
        g_c0[o] = v;
    }
}

// ---------------- K7b: fold proj -> A,B + border taps ----------------
__global__ void k_ab(const float* __restrict__ Wr, const float* __restrict__ Wi,
                     const float* __restrict__ br, const float* __restrict__ bi) {
    int o = blockIdx.x, tid = threadIdx.x;
    int cp = tid / 9, t = tid % 9;
    __shared__ float sP[576], sQ[576];
    sP[tid] = g_P[o*576 + tid];
    sQ[tid] = g_Q[o*576 + tid];
    __syncthreads();
    float a = 0.f, bb = 0.f;
    for (int cc = 0; cc < C_; cc++) {
        float p = sP[cc*9 + t], q = sQ[cc*9 + t];
        float wr = Wr[cc*C_ + cp], wi = Wi[cc*C_ + cp];
        a  += p * wr + q * wi;
        bb += -p * wi + q * wr;
    }
    g_A[o*576 + tid]  = a;
    g_Bk[o*576 + tid] = bb;
    if (tid < 9) {
        float tt = 0.f;
        for (int cc = 0; cc < C_; cc++)
            tt += sP[cc*9 + tid]*br[cc] + sQ[cc*9 + tid]*bi[cc];
        g_T[o*9 + tid] = tt;
    }
}

// ---------------- K7c: pack conv weights ----------------
__global__ void k_bprep() {
    int t = blockIdx.x >> 3;
    int base = (blockIdx.x & 7) * 1024;
    for (int j = threadIdx.x; j < 1024; j += 256) {
        int i = base + j;
        int n = i >> 7, k = i & 127;
        int ci = k >> 1, reim = k & 1;
        float wv = reim ? g_Bk[n*576 + ci*9 + t] : g_A[n*576 + ci*9 + t];
        int chunk = k >> 3;
        g_Bw[t*8192 + n*128 + ((chunk ^ (n & 7)) << 3) + (k & 7)] = __float2half(wv);
    }
}

// ---------------- K7d: bias + border-tap field ----------------
__global__ void k_bias() {
    int o = blockIdx.x;
    float c0 = g_c0[o];
    float T[9];
    #pragma unroll
    for (int t = 0; t < 9; t++) T[t] = g_T[o*9 + t];
    for (int i = threadIdx.x; i < SW_; i += 256) {
        int s = i >> 7, w = i & 127;
        float b = c0;
        #pragma unroll
        for (int t = 0; t < 9; t++) {
            int ds = t/3 - 1, dw = t%3 - 1;
            if (((unsigned)(s + ds) < (unsigned)S_) && ((unsigned)(w + dw) < (unsigned)W_))
                b += T[t];
        }
        g_bias[o*SW_ + i] = b;
    }
}

// ---------------- K3: MLP ----------------
__global__ void k_mlp(const float* __restrict__ w1, const float* __restrict__ b1,
                      const float* __restrict__ w2, const float* __restrict__ b2,
                      const float* __restrict__ fscale) {
    __shared__ float sc[C_], shid[H_], sf[CR_*2];
    int bl = blockIdx.x, tid = threadIdx.x;
    if (tid < C_) sc[tid] = g_ctx[bl*C_ + tid];
    __syncthreads();
    if (tid < H_) {
        float v = b1[tid];
        for (int cc = 0; cc < C_; cc++) v += sc[cc] * w1[cc*H_ + tid];
        shid[tid] = tanhf(v);
    }
    __syncthreads();
    for (int k = tid; k < CR_*2; k += 256) {
        float v = b2[k];
        #pragma unroll
        for (int j = 0; j < H_; j++) v += shid[j] * w2[j*(CR_*2) + k];
        sf[k] = v;
    }
    __syncthreads();
    float fs = *fscale;
    for (int cr = tid; cr < CR_; cr += 256) {
        float ga = g_gamma[cr];
        g_mod_re[bl*CR_ + cr] = ga * (1.f + fs * sf[2*cr]);
        g_mod_im[bl*CR_ + cr] = ga * (fs * sf[2*cr + 1]);
    }
}

// ---------------- K4: low-rank projection via mma.sync + ctx ----------------
// dyn smem: xT fp16 [w=128][s=64] swz (16384) + U' fp16 [n=64][k=64] swz (8192)
//         + V fp32 interleaved [w][r]{re,im} (32768) + red (1024)
#define SMEM_U_BYTES (16384 + 8192 + 32768 + 1024)
__global__ void __launch_bounds__(128) k_u_mma(const float* __restrict__ x,
        const float* __restrict__ Ur, const float* __restrict__ Ui,
        const float* __restrict__ Vr, const float* __restrict__ Vi) {
    extern __shared__ __align__(16) char smu[];
    __half* sXT = (__half*)smu;
    __half* sUp = (__half*)(smu + 16384);
    float*  sV  = (float*)(smu + 16384 + 8192);
    float*  sred = (float*)(smu + 16384 + 8192 + 32768);
    int tid = threadIdx.x, lane = tid & 31, warp = tid >> 5;
    int blc = blockIdx.x, c = blc & 63;

    // stage x^T (coalesced read, swizzled fp16 transpose write) + ctx sum
    const float* xp = x + (size_t)blc * SW_;
    float csum = 0.f;
    for (int i = tid; i < SW_; i += 128) {
        int s = i >> 7, w = i & 127;
        float xv = xp[i];
        csum += xv;
        int off = w*128 + ((((s >> 3) ^ (w & 7))) << 4) + (s & 7)*2;
        *(__half*)((char*)sXT + off) = __float2half(xv);
    }
    // stage U' [n][k]: n=2r -> Ur, n=2r+1 -> -Ui (conj folded in)
    for (int i = tid; i < 64*64; i += 128) {
        int n = i >> 6, k = i & 63;
        int r = n >> 1;
        float v = Ur[c*2048 + k*32 + r];
        if (n & 1) v = -Ui[c*2048 + k*32 + r];
        int off = n*128 + ((((k >> 3) ^ (n & 7))) << 4) + (k & 7)*2;
        *(__half*)((char*)sUp + off) = __float2half(v);
    }
    // stage V interleaved
    for (int i = tid; i < W_*R_; i += 128) {
        sV[i*2]     = Vr[c*4096 + i];
        sV[i*2 + 1] = Vi[c*4096 + i];
    }
    csum = blockReduceSum(csum, sred);
    if (tid == 0) g_ctx[blc] = csum * (1.f / (float)SW_);
    __syncthreads();

    uint32_t sXu = smem_u32(sXT), sUu = smem_u32(sUp);
    int wbase = warp * 32;
    float acc[2][8][4];
    #pragma unroll
    for (int mt = 0; mt < 2; mt++)
        #pragma unroll
        for (int nt = 0; nt < 8; nt++)
            #pragma unroll
            for (int j = 0; j < 4; j++) acc[mt][nt][j] = 0.f;

    #pragma unroll
    for (int ks = 0; ks < 4; ks++) {
        uint32_t a0[2], a1[2], a2[2], a3[2];
        #pragma unroll
        for (int mt = 0; mt < 2; mt++) {
            int row = wbase + mt*16 + (lane & 15);
            int cblk = ks*2 + (lane >> 4);
            uint32_t aaddr = sXu + row*128 + (uint32_t)((cblk ^ (row & 7)) << 4);
            asm volatile("ldmatrix.sync.aligned.m8n8.x4.shared.b16 {%0,%1,%2,%3}, [%4];"
                         : "=r"(a0[mt]), "=r"(a1[mt]), "=r"(a2[mt]), "=r"(a3[mt]) : "r"(aaddr));
        }
        #pragma unroll
        for (int nt = 0; nt < 8; nt++) {
            int n = nt*8 + (lane & 7);
            int cb = ks*2 + ((lane >> 3) & 1);
            uint32_t baddr = sUu + n*128 + (uint32_t)((cb ^ (n & 7)) << 4);
            uint32_t b0, b1;
            asm volatile("ldmatrix.sync.aligned.m8n8.x2.shared.b16 {%0,%1}, [%2];"
                         : "=r"(b0), "=r"(b1) : "r"(baddr));
            #pragma unroll
            for (int mt = 0; mt < 2; mt++)
                asm volatile("mma.sync.aligned.m16n8k16.row.col.f32.f16.f16.f32 "
                             "{%0,%1,%2,%3}, {%4,%5,%6,%7}, {%8,%9}, {%0,%1,%2,%3};"
                             : "+f"(acc[mt][nt][0]), "+f"(acc[mt][nt][1]),
                               "+f"(acc[mt][nt][2]), "+f"(acc[mt][nt][3])
                             : "r"(a0[mt]), "r"(a1[mt]), "r"(a2[mt]), "r"(a3[mt]),
                               "r"(b0), "r"(b1));
        }
    }
    // epilogue: contract with conj(V), reduce over w
    int g = lane >> 2, tq = lane & 3;
    float pre[8], pim[8];
    #pragma unroll
    for (int nt = 0; nt < 8; nt++) { pre[nt] = 0.f; pim[nt] = 0.f; }
    #pragma unroll
    for (int mt = 0; mt < 2; mt++) {
        int w1 = wbase + mt*16 + g, w2 = w1 + 8;
        #pragma unroll
        for (int nt = 0; nt < 8; nt++) {
            int r = nt*4 + tq;
            float vr1 = sV[(w1*32 + r)*2], vi1 = sV[(w1*32 + r)*2 + 1];
            float vr2 = sV[(w2*32 + r)*2], vi2 = sV[(w2*32 + r)*2 + 1];
            float ar = acc[mt][nt][0], ai = acc[mt][nt][1];
            float br = acc[mt][nt][2], bi = acc[mt][nt][3];
            pre[nt] += ar*vr1 + ai*vi1 + br*vr2 + bi*vi2;
            pim[nt] += ai*vr1 - ar*vi1 + bi*vr2 - br*vi2;
        }
    }
    #pragma unroll
    for (int nt = 0; nt < 8; nt++) {
        #pragma unroll
        for (int o = 16; o >= 4; o >>= 1) {
            pre[nt] += __shfl_down_sync(0xffffffffu, pre[nt], o);
            pim[nt] += __shfl_down_sync(0xffffffffu, pim[nt], o);
        }
    }
    __syncthreads();
    if (lane < 4) {
        #pragma unroll
        for (int nt = 0; nt < 8; nt++) {
            int r = nt*4 + lane;
            sred[warp*64 + r*2]     = pre[nt];
            sred[warp*64 + r*2 + 1] = pim[nt];
        }
    }
    __syncthreads();
    if (tid < 32) {
        int r = tid;
        float ur = 0.f, ui = 0.f;
        #pragma unroll
        for (int wp = 0; wp < 4; wp++) {
            ur += sred[wp*64 + r*2];
            ui += sred[wp*64 + r*2 + 1];
        }
        g_u_re[blc*R_ + r] = ur;
        g_u_im[blc*R_ + r] = ui;
    }
}

// ---------------- K5: scan (applies modulation) ----------------
__global__ void k_scan() {
    int t = blockIdx.x * 256 + threadIdx.x;
    int b = t >> 11;
    int cr = t & (CR_ - 1);
    float lr = g_lam_re[cr], li = g_lam_im[cr];
    float hr = 0.f, hi = 0.f;
    #pragma unroll
    for (int l = 0; l < L_; l++) {
        int idx = (b*L_ + l)*CR_ + cr;
        float ur_raw = g_u_re[idx], ui_raw = g_u_im[idx];
        float mr = g_mod_re[idx], mi = g_mod_im[idx];
        float ur = mr*ur_raw - mi*ui_raw;
        float ui = mr*ui_raw + mi*ur_raw;
        float nr = lr*hr - li*hi + ur;
        float ni = lr*hi + li*hr + ui;
        hr = nr; hi = ni;
        g_h_re[idx] = hr;
        g_h_im[idx] = hi;
    }
}

// ---------------- K6: reconstruct via mma.sync -> half2 planes ----------------
__global__ void __launch_bounds__(256) k_recon_mma(
        const float* __restrict__ Ur, const float* __restrict__ Ui,
        const float* __restrict__ Vr, const float* __restrict__ Vi) {
    __shared__ __align__(16) __half sA[64*64];
    __shared__ __align__(16) __half sBv[256*64];
    __shared__ float sh[64];
    int tid = threadIdx.x, lane = tid & 31, warp = tid >> 5;
    int blc = blockIdx.x, c = blc & 63;
    if (tid < 64) sh[tid] = (tid < 32) ? g_h_re[blc*R_ + tid] : g_h_im[blc*R_ + tid - 32];
    __syncthreads();
    // A tile: g = h*U (complex), k=2r -> re, 2r+1 -> im
    for (int i = tid; i < 2048; i += 256) {
        int s = i >> 5, r = i & 31;
        float hr = sh[r], hi = sh[32 + r];
        float ur = Ur[c*2048 + s*32 + r], ui = Ui[c*2048 + s*32 + r];
        float gr = hr*ur - hi*ui;
        float gi = hr*ui + hi*ur;
        int off = s*128 + ((((r >> 2) ^ (s & 7))) << 4) + (r & 3)*4;
        __half2 h2 = __floats2half2_rn(gr, gi);
        *(uint32_t*)((char*)sA + off) = *(uint32_t*)&h2;
    }
    // B tile: n=(w,nc), k=(r,kc): [Vr, -Vi; Vi, Vr]
    for (int i = tid; i < 256*64; i += 256) {
        int n = i >> 6, k = i & 63;
        int w = n >> 1, nc = n & 1, r = k >> 1, kc = k & 1;
        float vr = Vr[c*4096 + w*32 + r], vi = Vi[c*4096 + w*32 + r];
        float v = nc ? (kc ? vr : vi) : (kc ? -vi : vr);
        int off = n*128 + ((((k >> 3) ^ (n & 7))) << 4) + (k & 7)*2;
        *(__half*)((char*)sBv + off) = __float2half(v);
    }
    __syncthreads();

    uint32_t sAu = smem_u32(sA), sBu = smem_u32(sBv);
    int mt = warp & 3, nh = warp >> 2;
    int mrow = mt * 16;
    float acc[16][4];
    #pragma unroll
    for (int nt = 0; nt < 16; nt++)
        #pragma unroll
        for (int j = 0; j < 4; j++) acc[nt][j] = 0.f;

    #pragma unroll
    for (int ks = 0; ks < 4; ks++) {
        int row = mrow + (lane & 15);
        int cblk = ks*2 + (lane >> 4);
        uint32_t aaddr = sAu + row*128 + (uint32_t)((cblk ^ (row & 7)) << 4);
        uint32_t a0, a1, a2, a3;
        asm volatile("ldmatrix.sync.aligned.m8n8.x4.shared.b16 {%0,%1,%2,%3}, [%4];"
                     : "=r"(a0), "=r"(a1), "=r"(a2), "=r"(a3) : "r"(aaddr));
        #pragma unroll
        for (int nt = 0; nt < 16; nt++) {
            int n = (nh*16 + nt)*8 + (lane & 7);
            int cb = ks*2 + ((lane >> 3) & 1);
            uint32_t baddr = sBu + n*128 + (uint32_t)((cb ^ (n & 7)) << 4);
            uint32_t b0, b1;
            asm volatile("ldmatrix.sync.aligned.m8n8.x2.shared.b16 {%0,%1}, [%2];"
                         : "=r"(b0), "=r"(b1) : "r"(baddr));
            asm volatile("mma.sync.aligned.m16n8k16.row.col.f32.f16.f16.f32 "
                         "{%0,%1,%2,%3}, {%4,%5,%6,%7}, {%8,%9}, {%0,%1,%2,%3};"
                         : "+f"(acc[nt][0]), "+f"(acc[nt][1]), "+f"(acc[nt][2]), "+f"(acc[nt][3])
                         : "r"(a0), "r"(a1), "r"(a2), "r"(a3), "r"(b0), "r"(b1));
        }
    }
    // epilogue: pack half2 (re,im) -> g_yh
    int g = lane >> 2, tq = lane & 3;
    uint32_t* py = g_yh + (size_t)blc*SW_;
    #pragma unroll
    for (int nt = 0; nt < 16; nt++) {
        int w = (nh*16 + nt)*4 + tq;
        __half2 h1 = __floats2half2_rn(acc[nt][0], acc[nt][1]);
        __half2 h2 = __floats2half2_rn(acc[nt][2], acc[nt][3]);
        py[(mrow + g)*W_ + w]     = *(uint32_t*)&h1;
        py[(mrow + g + 8)*W_ + w] = *(uint32_t*)&h2;
    }
}

// ---------------- K8: fp16 mma.sync conv-GEMM, 2 s-rows per CTA ----------------
#define CONV_SMEM (133120 + 16384)
__global__ void __launch_bounds__(512) k_conv_mma() {
    extern __shared__ __align__(16) char smc[];
    char* sB = smc + 133120;
    int tid = threadIdx.x, lane = tid & 31, warp = tid >> 5;
    int bl = blockIdx.x >> 5, s0 = (blockIdx.x & 31) * 2;

    const uint32_t* ybl = g_yh + (size_t)bl * (C_*SW_);
    for (int i = tid; i < 4*130*64; i += 512) {
        int ci = i / 520, rem = i % 520;
        int ds = rem / 130, pw = rem % 130;
        int sr = s0 + ds - 1, w = pw - 1;
        uint32_t v = 0u;
        if (((unsigned)sr < (unsigned)S_) && ((unsigned)w < (unsigned)W_))
            v = ybl[(size_t)ci*SW_ + sr*W_ + w];
        int phys = ds*33280 + pw*256 + ((((ci >> 2) ^ (pw & 7))) << 4) + (ci & 3)*4;
        *(uint32_t*)(smc + phys) = v;
    }

    float acc[8][4];
    #pragma unroll
    for (int nt = 0; nt < 8; nt++)
        #pragma unroll
        for (int j = 0; j < 4; j++) acc[nt][j] = 0.f;

    uint32_t sAu = smem_u32(smc), sBu = smem_u32(sB);
    int s_row = warp >> 3;
    int wbase = (warp & 7) * 16;

    #pragma unroll 1
    for (int t = 0; t < 9; t++) {
        __syncthreads();
        {
            const uint4* src = (const uint4*)(g_Bw + t*8192);
            uint4* dst = (uint4*)sB;
            dst[tid]       = src[tid];
            dst[tid + 512] = src[tid + 512];
        }
        __syncthreads();
        int tx = t % 3, ds = s_row + t / 3;
        #pragma unroll 1
        for (int ks = 0; ks < 8; ks++) {
            int row = wbase + (lane & 15) + tx;
            int cblk = ks*2 + (lane >> 4);
            uint32_t aaddr = sAu + ds*33280 + row*256 + (uint32_t)((cblk ^ (row & 7)) << 4);
            uint32_t a0, a1, a2, a3;
            asm volatile("ldmatrix.sync.aligned.m8n8.x4.shared.b16 {%0,%1,%2,%3}, [%4];"
                         : "=r"(a0), "=r"(a1), "=r"(a2), "=r"(a3) : "r"(aaddr));
            #pragma unroll
            for (int nt = 0; nt < 8; nt++) {
                int n = nt*8 + (lane & 7);
                int cb = ks*2 + ((lane >> 3) & 1);
                uint32_t baddr = sBu + n*256 + (uint32_t)((cb ^ (n & 7)) << 4);
                uint32_t b0, b1;
                asm volatile("ldmatrix.sync.aligned.m8n8.x2.shared.b16 {%0,%1}, [%2];"
                             : "=r"(b0), "=r"(b1) : "r"(baddr));
                asm volatile("mma.sync.aligned.m16n8k16.row.col.f32.f16.f16.f32 "
                             "{%0,%1,%2,%3}, {%4,%5,%6,%7}, {%8,%9}, {%0,%1,%2,%3};"
                             : "+f"(acc[nt][0]), "+f"(acc[nt][1]), "+f"(acc[nt][2]), "+f"(acc[nt][3])
                             : "r"(a0), "r"(a1), "r"(a2), "r"(a3), "r"(b0), "r"(b1));
            }
        }
    }
    int g = lane >> 2, tq = lane & 3;
    float* ob = g_fused + (size_t)bl * (C_*SW_) + (s0 + s_row)*W_ + wbase + g;
    #pragma unroll
    for (int nt = 0; nt < 8; nt++) {
        int o0 = nt*8 + 2*tq;
        ob[(size_t)o0*SW_]           = acc[nt][0];
        ob[(size_t)(o0 + 1)*SW_]     = acc[nt][1];
        ob[(size_t)o0*SW_ + 8]       = acc[nt][2];
        ob[(size_t)(o0 + 1)*SW_ + 8] = acc[nt][3];
    }
}

// ---------------- K9: LayerNorm (+ bias field) + residual ----------------
__global__ void k_ln(const float* __restrict__ x, const float* __restrict__ lng,
                     const float* __restrict__ lnb, float* __restrict__ out) {
    __shared__ float sbuf1[8], sbuf2[8];
    __shared__ float s_mu, s_rstd;
    int blc = blockIdx.x, tid = threadIdx.x;
    int o = blc % C_;
    const float* fp = g_fused + (size_t)blc * SW_;
    const float* bp = g_bias + (size_t)o * SW_;
    float v[32];
    float sum = 0.f, sq = 0.f;
    #pragma unroll
    for (int k = 0; k < 32; k++) {
        int i = tid + 256*k;
        float t = fp[i] + bp[i];
        v[k] = t; sum += t; sq += t*t;
    }
    float ts = blockReduceSum(sum, sbuf1);
    __syncthreads();
    float tq = blockReduceSum(sq, sbuf2);
    if (tid == 0) {
        float mu = ts * (1.f / (float)SW_);
        float var = tq * (1.f / (float)SW_) - mu*mu;
        s_mu = mu;
        s_rstd = rsqrtf(var + 1e-5f);
    }
    __syncthreads();
    float mu = s_mu, rstd = s_rstd;
    const float* xp = x + (size_t)blc * SW_;
    float* op = out + (size_t)blc * SW_;
    #pragma unroll
    for (int k = 0; k < 32; k++) {
        int i = tid + 256*k;
        op[i] = (v[k] - mu) * rstd * lng[i] + lnb[i] + xp[i];
    }
}

// ---------------- launch ----------------
extern "C" void kernel_launch(void* const* d_in, const int* in_sizes, int n_in,
                              void* d_out, int out_size) {
    const float* x         = (const float*)d_in[0];
    const float* nu_log    = (const float*)d_in[1];
    const float* theta_log = (const float*)d_in[2];
    const float* disp_nu   = (const float*)d_in[3];
    const float* disp_th   = (const float*)d_in[4];
    const float* mlp_w1    = (const float*)d_in[5];
    const float* mlp_b1    = (const float*)d_in[6];
    const float* mlp_w2    = (const float*)d_in[7];
    const float* mlp_b2    = (const float*)d_in[8];
    const float* fscale    = (const float*)d_in[9];
    const float* U_row_r   = (const float*)d_in[10];
    const float* U_row_i   = (const float*)d_in[11];
    const float* V_col_r   = (const float*)d_in[12];
    const float* V_col_i   = (const float*)d_in[13];
    const float* proj_W_r  = (const float*)d_in[14];
    const float* proj_W_i  = (const float*)d_in[15];
    const float* proj_b_r  = (const float*)d_in[16];
    const float* proj_b_i  = (const float*)d_in[17];
    const float* convr_k   = (const float*)d_in[18];
    const float* convr_b   = (const float*)d_in[19];
    const float* convi_k   = (const float*)d_in[20];
    const float* convi_b   = (const float*)d_in[21];
    const float* fuse_k    = (const float*)d_in[22];
    const float* fuse_b    = (const float*)d_in[23];
    const float* ln_g      = (const float*)d_in[24];
    const float* ln_b      = (const float*)d_in[25];
    float* out = (float*)d_out;

    cudaFuncSetAttribute(k_u_mma,    cudaFuncAttributeMaxDynamicSharedMemorySize, SMEM_U_BYTES);
    cudaFuncSetAttribute(k_conv_mma, cudaFuncAttributeMaxDynamicSharedMemorySize, CONV_SMEM);

    k_poles<<<(CR_ + 255)/256, 256>>>(nu_log, theta_log, disp_nu, disp_th);
    k_pq<<<C_, 576>>>(fuse_k, convr_k, convi_k, convr_b, convi_b, fuse_b);
    k_ab<<<C_, 576>>>(proj_W_r, proj_W_i, proj_b_r, proj_b_i);
    k_bprep<<<72, 256>>>();
    k_bias<<<C_, 256>>>();
    k_u_mma<<<PLANES_, 128, SMEM_U_BYTES>>>(x, U_row_r, U_row_i, V_col_r, V_col_i);
    k_mlp<<<BL_, 256>>>(mlp_w1, mlp_b1, mlp_w2, mlp_b2, fscale);
    k_scan<<<16, 256>>>();
    k_recon_mma<<<PLANES_, 256>>>(U_row_r, U_row_i, V_col_r, V_col_i);
    k_conv_mma<<<1024, 512, CONV_SMEM>>>();
    k_ln<<<PLANES_, 256>>>(x, ln_g, ln_b, out);
}

// round 8
// speedup vs baseline: 8.3689x; 1.1007x over previous
#include <cuda_runtime.h>
#include <cuda_fp16.h>
#include <math.h>
#include <stdint.h>

#define B_  2
#define L_  16
#define C_  64
#define S_  64
#define W_  128
#define R_  32
#define H_  32
#define BL_ (B_*L_)
#define SW_ (S_*W_)
#define CR_ (C_*R_)
#define PLANES_ (BL_*C_)
#define NELEM_ (PLANES_*SW_)

// ---------------- device scratch ----------------
__device__ float    g_lam_re[CR_], g_lam_im[CR_], g_gamma[CR_];
__device__ float    g_ctx[BL_*C_];
__device__ float    g_mod_re[BL_*CR_], g_mod_im[BL_*CR_];
__device__ float    g_u_re[BL_*CR_],  g_u_im[BL_*CR_];
__device__ float    g_h_re[BL_*CR_],  g_h_im[BL_*CR_];
__device__ float    g_P[C_*C_*9], g_Q[C_*C_*9];
__device__ float    g_A[C_*C_*9], g_Bk[C_*C_*9];
__device__ float    g_T[C_*9], g_c0[C_];
__device__ uint32_t g_yh[NELEM_];   // half2 (re,im) planes
__device__ float    g_fused[NELEM_];
__device__ __half   g_Bw[9*8192];   // per-tap swizzled [o=64][k=128] fp16 weights
__device__ float    g_bias[C_*SW_]; // bias + border-tap field

// ---------------- helpers ----------------
__device__ __forceinline__ float blockReduceSum(float v, float* sbuf) {
    int lane = threadIdx.x & 31, warp = threadIdx.x >> 5;
    #pragma unroll
    for (int o = 16; o > 0; o >>= 1) v += __shfl_down_sync(0xffffffffu, v, o);
    if (lane == 0) sbuf[warp] = v;
    __syncthreads();
    int nw = blockDim.x >> 5;
    v = (threadIdx.x < nw) ? sbuf[threadIdx.x] : 0.f;
    if (warp == 0) {
        #pragma unroll
        for (int o = 16; o > 0; o >>= 1) v += __shfl_down_sync(0xffffffffu, v, o);
    }
    return v;
}
__device__ __forceinline__ uint32_t smem_u32(const void* p) {
    uint32_t a;
    asm("{ .reg .u64 t; cvta.to.shared.u64 t, %1; cvt.u32.u64 %0, t; }" : "=r"(a) : "l"(p));
    return a;
}

// ---------------- K1: poles ----------------
__global__ void k_poles(const float* __restrict__ nu_log, const float* __restrict__ th_log,
                        const float* __restrict__ dnu, const float* __restrict__ dth) {
    int i = blockIdx.x * 256 + threadIdx.x;
    if (i >= CR_) return;
    float nu = expf(nu_log[i] + dnu[i]);
    float th = expf(th_log[i] + dth[i]);
    float el = expf(-nu);
    g_lam_re[i] = el * cosf(th);
    g_lam_im[i] = el * sinf(th);
    g_gamma[i]  = sqrtf(fmaxf(1.f - el * el, 1e-6f));
}

// ---------------- K7a: P,Q = fuse ∘ conv ----------------
__global__ void k_pq(const float* __restrict__ fuse_k, const float* __restrict__ convr_k,
                     const float* __restrict__ convi_k, const float* __restrict__ convr_b,
                     const float* __restrict__ convi_b, const float* __restrict__ fuse_b) {
    int o = blockIdx.x, tid = threadIdx.x;
    __shared__ float sF1[C_], sF2[C_];
    if (tid < 64)       sF1[tid]      = fuse_k[o*128 + tid];
    else if (tid < 128) sF2[tid - 64] = fuse_k[o*128 + tid];
    __syncthreads();
    float p = 0.f, q = 0.f;
    for (int m = 0; m < C_; m++) {
        p += sF1[m] * convr_k[m*576 + tid];
        q += sF2[m] * convi_k[m*576 + tid];
    }
    g_P[o*576 + tid] = p;
    g_Q[o*576 + tid] = q;
    if (tid == 0) {
        float v = fuse_b[o];
        for (int m = 0; m < C_; m++) v += sF1[m]*convr_b[m] + sF2[m]*convi_b[m];
        g_c0[o] = v;
    }
}

// ---------------- K7b: fold proj -> A,B + border taps ----------------
__global__ void k_ab(const float* __restrict__ Wr, const float* __restrict__ Wi,
                     const float* __restrict__ br, const float* __restrict__ bi) {
    int o = blockIdx.x, tid = threadIdx.x;
    int cp = tid / 9, t = tid % 9;
    __shared__ float sP[576], sQ[576];
    sP[tid] = g_P[o*576 + tid];
    sQ[tid] = g_Q[o*576 + tid];
    __syncthreads();
    float a = 0.f, bb = 0.f;
    for (int cc = 0; cc < C_; cc++) {
        float p = sP[cc*9 + t], q = sQ[cc*9 + t];
        float wr = Wr[cc*C_ + cp], wi = Wi[cc*C_ + cp];
        a  += p * wr + q * wi;
        bb += -p * wi + q * wr;
    }
    g_A[o*576 + tid]  = a;
    g_Bk[o*576 + tid] = bb;
    if (tid < 9) {
        float tt = 0.f;
        for (int cc = 0; cc < C_; cc++)
            tt += sP[cc*9 + tid]*br[cc] + sQ[cc*9 + tid]*bi[cc];
        g_T[o*9 + tid] = tt;
    }
}

// ---------------- K7c: pack conv weights ----------------
__global__ void k_bprep() {
    int t = blockIdx.x >> 3;
    int base = (blockIdx.x & 7) * 1024;
    for (int j = threadIdx.x; j < 1024; j += 256) {
        int i = base + j;
        int n = i >> 7, k = i & 127;
        int ci = k >> 1, reim = k & 1;
        float wv = reim ? g_Bk[n*576 + ci*9 + t] : g_A[n*576 + ci*9 + t];
        int chunk = k >> 3;
        g_Bw[t*8192 + n*128 + ((chunk ^ (n & 7)) << 3) + (k & 7)] = __float2half(wv);
    }
}

// ---------------- K7d: bias + border-tap field ----------------
__global__ void k_bias() {
    int o = blockIdx.x;
    float c0 = g_c0[o];
    float T[9];
    #pragma unroll
    for (int t = 0; t < 9; t++) T[t] = g_T[o*9 + t];
    for (int i = threadIdx.x; i < SW_; i += 256) {
        int s = i >> 7, w = i & 127;
        float b = c0;
        #pragma unroll
        for (int t = 0; t < 9; t++) {
            int ds = t/3 - 1, dw = t%3 - 1;
            if (((unsigned)(s + ds) < (unsigned)S_) && ((unsigned)(w + dw) < (unsigned)W_))
                b += T[t];
        }
        g_bias[o*SW_ + i] = b;
    }
}

// ---------------- K3: MLP ----------------
__global__ void k_mlp(const float* __restrict__ w1, const float* __restrict__ b1,
                      const float* __restrict__ w2, const float* __restrict__ b2,
                      const float* __restrict__ fscale) {
    __shared__ float sc[C_], shid[H_], sf[CR_*2];
    int bl = blockIdx.x, tid = threadIdx.x;
    if (tid < C_) sc[tid] = g_ctx[bl*C_ + tid];
    __syncthreads();
    if (tid < H_) {
        float v = b1[tid];
        for (int cc = 0; cc < C_; cc++) v += sc[cc] * w1[cc*H_ + tid];
        shid[tid] = tanhf(v);
    }
    __syncthreads();
    for (int k = tid; k < CR_*2; k += 256) {
        float v = b2[k];
        #pragma unroll
        for (int j = 0; j < H_; j++) v += shid[j] * w2[j*(CR_*2) + k];
        sf[k] = v;
    }
    __syncthreads();
    float fs = *fscale;
    for (int cr = tid; cr < CR_; cr += 256) {
        float ga = g_gamma[cr];
        g_mod_re[bl*CR_ + cr] = ga * (1.f + fs * sf[2*cr]);
        g_mod_im[bl*CR_ + cr] = ga * (fs * sf[2*cr + 1]);
    }
}

// ---------------- K4: low-rank projection via mma.sync + ctx (256 threads) ----------------
// dyn smem: xT fp16 swz (16384) + U' fp16 swz (8192) + V fp32 (32768) + red (2048)
#define SMEM_U_BYTES (16384 + 8192 + 32768 + 2048)
__global__ void __launch_bounds__(256) k_u_mma(const float* __restrict__ x,
        const float* __restrict__ Ur, const float* __restrict__ Ui,
        const float* __restrict__ Vr, const float* __restrict__ Vi) {
    extern __shared__ __align__(16) char smu[];
    __half* sXT = (__half*)smu;
    __half* sUp = (__half*)(smu + 16384);
    float*  sV  = (float*)(smu + 16384 + 8192);
    float*  sred = (float*)(smu + 16384 + 8192 + 32768);
    int tid = threadIdx.x, lane = tid & 31, warp = tid >> 5;
    int blc = blockIdx.x, c = blc & 63;

    const float* xp = x + (size_t)blc * SW_;
    float csum = 0.f;
    for (int i = tid; i < SW_; i += 256) {
        int s = i >> 7, w = i & 127;
        float xv = xp[i];
        csum += xv;
        int off = w*128 + ((((s >> 3) ^ (w & 7))) << 4) + (s & 7)*2;
        *(__half*)((char*)sXT + off) = __float2half(xv);
    }
    for (int i = tid; i < 64*64; i += 256) {
        int n = i >> 6, k = i & 63;
        int r = n >> 1;
        float v = Ur[c*2048 + k*32 + r];
        if (n & 1) v = -Ui[c*2048 + k*32 + r];
        int off = n*128 + ((((k >> 3) ^ (n & 7))) << 4) + (k & 7)*2;
        *(__half*)((char*)sUp + off) = __float2half(v);
    }
    for (int i = tid; i < W_*R_; i += 256) {
        sV[i*2]     = Vr[c*4096 + i];
        sV[i*2 + 1] = Vi[c*4096 + i];
    }
    csum = blockReduceSum(csum, sred);
    if (tid == 0) g_ctx[blc] = csum * (1.f / (float)SW_);
    __syncthreads();

    uint32_t sXu = smem_u32(sXT), sUu = smem_u32(sUp);
    int wbase = warp * 16;
    float acc[8][4];
    #pragma unroll
    for (int nt = 0; nt < 8; nt++)
        #pragma unroll
        for (int j = 0; j < 4; j++) acc[nt][j] = 0.f;

    #pragma unroll
    for (int ks = 0; ks < 4; ks++) {
        int row = wbase + (lane & 15);
        int cblk = ks*2 + (lane >> 4);
        uint32_t aaddr = sXu + row*128 + (uint32_t)((cblk ^ (row & 7)) << 4);
        uint32_t a0, a1, a2, a3;
        asm volatile("ldmatrix.sync.aligned.m8n8.x4.shared.b16 {%0,%1,%2,%3}, [%4];"
                     : "=r"(a0), "=r"(a1), "=r"(a2), "=r"(a3) : "r"(aaddr));
        #pragma unroll
        for (int nt = 0; nt < 8; nt++) {
            int n = nt*8 + (lane & 7);
            int cb = ks*2 + ((lane >> 3) & 1);
            uint32_t baddr = sUu + n*128 + (uint32_t)((cb ^ (n & 7)) << 4);
            uint32_t b0, b1;
            asm volatile("ldmatrix.sync.aligned.m8n8.x2.shared.b16 {%0,%1}, [%2];"
                         : "=r"(b0), "=r"(b1) : "r"(baddr));
            asm volatile("mma.sync.aligned.m16n8k16.row.col.f32.f16.f16.f32 "
                         "{%0,%1,%2,%3}, {%4,%5,%6,%7}, {%8,%9}, {%0,%1,%2,%3};"
                         : "+f"(acc[nt][0]), "+f"(acc[nt][1]), "+f"(acc[nt][2]), "+f"(acc[nt][3])
                         : "r"(a0), "r"(a1), "r"(a2), "r"(a3), "r"(b0), "r"(b1));
        }
    }
    // epilogue: contract with conj(V), reduce over w
    int g = lane >> 2, tq = lane & 3;
    float pre[8], pim[8];
    #pragma unroll
    for (int nt = 0; nt < 8; nt++) { pre[nt] = 0.f; pim[nt] = 0.f; }
    {
        int w1 = wbase + g, w2 = w1 + 8;
        #pragma unroll
        for (int nt = 0; nt < 8; nt++) {
            int r = nt*4 + tq;
            float vr1 = sV[(w1*32 + r)*2], vi1 = sV[(w1*32 + r)*2 + 1];
            float vr2 = sV[(w2*32 + r)*2], vi2 = sV[(w2*32 + r)*2 + 1];
            float ar = acc[nt][0], ai = acc[nt][1];
            float br = acc[nt][2], bi = acc[nt][3];
            pre[nt] += ar*vr1 + ai*vi1 + br*vr2 + bi*vi2;
            pim[nt] += ai*vr1 - ar*vi1 + bi*vr2 - br*vi2;
        }
    }
    #pragma unroll
    for (int nt = 0; nt < 8; nt++) {
        #pragma unroll
        for (int o = 16; o >= 4; o >>= 1) {
            pre[nt] += __shfl_down_sync(0xffffffffu, pre[nt], o);
            pim[nt] += __shfl_down_sync(0xffffffffu, pim[nt], o);
        }
    }
    __syncthreads();
    if (lane < 4) {
        #pragma unroll
        for (int nt = 0; nt < 8; nt++) {
            int r = nt*4 + lane;
            sred[warp*64 + r*2]     = pre[nt];
            sred[warp*64 + r*2 + 1] = pim[nt];
        }
    }
    __syncthreads();
    if (tid < 32) {
        int r = tid;
        float ur = 0.f, ui = 0.f;
        #pragma unroll
        for (int wp = 0; wp < 8; wp++) {
            ur += sred[wp*64 + r*2];
            ui += sred[wp*64 + r*2 + 1];
        }
        g_u_re[blc*R_ + r] = ur;
        g_u_im[blc*R_ + r] = ui;
    }
}

// ---------------- K5: scan (applies modulation) ----------------
__global__ void k_scan() {
    int t = blockIdx.x * 256 + threadIdx.x;
    int b = t >> 11;
    int cr = t & (CR_ - 1);
    float lr = g_lam_re[cr], li = g_lam_im[cr];
    float hr = 0.f, hi = 0.f;
    #pragma unroll
    for (int l = 0; l < L_; l++) {
        int idx = (b*L_ + l)*CR_ + cr;
        float ur_raw = g_u_re[idx], ui_raw = g_u_im[idx];
        float mr = g_mod_re[idx], mi = g_mod_im[idx];
        float ur = mr*ur_raw - mi*ui_raw;
        float ui = mr*ui_raw + mi*ur_raw;
        float nr = lr*hr - li*hi + ur;
        float ni = lr*hi + li*hr + ui;
        hr = nr; hi = ni;
        g_h_re[idx] = hr;
        g_h_im[idx] = hi;
    }
}

// ---------------- K6: reconstruct via mma.sync -> half2 planes ----------------
__global__ void __launch_bounds__(256) k_recon_mma(
        const float* __restrict__ Ur, const float* __restrict__ Ui,
        const float* __restrict__ Vr, const float* __restrict__ Vi) {
    __shared__ __align__(16) __half sA[64*64];
    __shared__ __align__(16) __half sBv[256*64];
    __shared__ float sh[64];
    int tid = threadIdx.x, lane = tid & 31, warp = tid >> 5;
    int blc = blockIdx.x, c = blc & 63;
    if (tid < 64) sh[tid] = (tid < 32) ? g_h_re[blc*R_ + tid] : g_h_im[blc*R_ + tid - 32];
    __syncthreads();
    for (int i = tid; i < 2048; i += 256) {
        int s = i >> 5, r = i & 31;
        float hr = sh[r], hi = sh[32 + r];
        float ur = Ur[c*2048 + s*32 + r], ui = Ui[c*2048 + s*32 + r];
        float gr = hr*ur - hi*ui;
        float gi = hr*ui + hi*ur;
        int off = s*128 + ((((r >> 2) ^ (s & 7))) << 4) + (r & 3)*4;
        __half2 h2 = __floats2half2_rn(gr, gi);
        *(uint32_t*)((char*)sA + off) = *(uint32_t*)&h2;
    }
    for (int i = tid; i < 256*64; i += 256) {
        int n = i >> 6, k = i & 63;
        int w = n >> 1, nc = n & 1, r = k >> 1, kc = k & 1;
        float vr = Vr[c*4096 + w*32 + r], vi = Vi[c*4096 + w*32 + r];
        float v = nc ? (kc ? vr : vi) : (kc ? -vi : vr);
        int off = n*128 + ((((k >> 3) ^ (n & 7))) << 4) + (k & 7)*2;
        *(__half*)((char*)sBv + off) = __float2half(v);
    }
    __syncthreads();

    uint32_t sAu = smem_u32(sA), sBu = smem_u32(sBv);
    int mt = warp & 3, nh = warp >> 2;
    int mrow = mt * 16;
    float acc[16][4];
    #pragma unroll
    for (int nt = 0; nt < 16; nt++)
        #pragma unroll
        for (int j = 0; j < 4; j++) acc[nt][j] = 0.f;

    #pragma unroll
    for (int ks = 0; ks < 4; ks++) {
        int row = mrow + (lane & 15);
        int cblk = ks*2 + (lane >> 4);
        uint32_t aaddr = sAu + row*128 + (uint32_t)((cblk ^ (row & 7)) << 4);
        uint32_t a0, a1, a2, a3;
        asm volatile("ldmatrix.sync.aligned.m8n8.x4.shared.b16 {%0,%1,%2,%3}, [%4];"
                     : "=r"(a0), "=r"(a1), "=r"(a2), "=r"(a3) : "r"(aaddr));
        #pragma unroll
        for (int nt = 0; nt < 16; nt++) {
            int n = (nh*16 + nt)*8 + (lane & 7);
            int cb = ks*2 + ((lane >> 3) & 1);
            uint32_t baddr = sBu + n*128 + (uint32_t)((cb ^ (n & 7)) << 4);
            uint32_t b0, b1;
            asm volatile("ldmatrix.sync.aligned.m8n8.x2.shared.b16 {%0,%1}, [%2];"
                         : "=r"(b0), "=r"(b1) : "r"(baddr));
            asm volatile("mma.sync.aligned.m16n8k16.row.col.f32.f16.f16.f32 "
                         "{%0,%1,%2,%3}, {%4,%5,%6,%7}, {%8,%9}, {%0,%1,%2,%3};"
                         : "+f"(acc[nt][0]), "+f"(acc[nt][1]), "+f"(acc[nt][2]), "+f"(acc[nt][3])
                         : "r"(a0), "r"(a1), "r"(a2), "r"(a3), "r"(b0), "r"(b1));
        }
    }
    int g = lane >> 2, tq = lane & 3;
    uint32_t* py = g_yh + (size_t)blc*SW_;
    #pragma unroll
    for (int nt = 0; nt < 16; nt++) {
        int w = (nh*16 + nt)*4 + tq;
        __half2 h1 = __floats2half2_rn(acc[nt][0], acc[nt][1]);
        __half2 h2 = __floats2half2_rn(acc[nt][2], acc[nt][3]);
        py[(mrow + g)*W_ + w]     = *(uint32_t*)&h1;
        py[(mrow + g + 8)*W_ + w] = *(uint32_t*)&h2;
    }
}

// ---------------- K8: fp16 mma.sync conv-GEMM, 4 s-rows per CTA, 2 A-tiles/warp ----------------
// grid 512 = bl*16 + squad; 512 threads = 16 warps.
// SMEM: staged rows [6][130][64] half2 swz (199680 B) + B tap tile (16384 B)
#define CONV_SMEM (199680 + 16384)
__global__ void __launch_bounds__(512) k_conv_mma() {
    extern __shared__ __align__(16) char smc[];
    char* sB = smc + 199680;
    int tid = threadIdx.x, lane = tid & 31, warp = tid >> 5;
    int bl = blockIdx.x >> 4, s0 = (blockIdx.x & 15) * 4;

    // stage 6 halo rows (s0-1 .. s0+4), coalesced over w
    const uint32_t* ybl = g_yh + (size_t)bl * (C_*SW_);
    for (int i = tid; i < 6*130*64; i += 512) {
        int ci = i / 780, rem = i % 780;
        int ds = rem / 130, pw = rem % 130;
        int sr = s0 + ds - 1, w = pw - 1;
        uint32_t v = 0u;
        if (((unsigned)sr < (unsigned)S_) && ((unsigned)w < (unsigned)W_))
            v = ybl[(size_t)ci*SW_ + sr*W_ + w];
        int phys = ds*33280 + pw*256 + ((((ci >> 2) ^ (pw & 7))) << 4) + (ci & 3)*4;
        *(uint32_t*)(smc + phys) = v;
    }

    float acc[2][8][4];
    #pragma unroll
    for (int mt = 0; mt < 2; mt++)
        #pragma unroll
        for (int nt = 0; nt < 8; nt++)
            #pragma unroll
            for (int j = 0; j < 4; j++) acc[mt][nt][j] = 0.f;

    uint32_t sAu = smem_u32(smc), sBu = smem_u32(sB);
    int s_row = warp >> 2;          // 0..3
    int wbase = (warp & 3) * 32;    // 0,32,64,96

    #pragma unroll 1
    for (int t = 0; t < 9; t++) {
        __syncthreads();
        {
            const uint4* src = (const uint4*)(g_Bw + t*8192);
            uint4* dst = (uint4*)sB;
            dst[tid]       = src[tid];
            dst[tid + 512] = src[tid + 512];
        }
        __syncthreads();
        int tx = t % 3, ds = s_row + t / 3;
        #pragma unroll 1
        for (int ks = 0; ks < 8; ks++) {
            uint32_t a0[2], a1[2], a2[2], a3[2];
            #pragma unroll
            for (int mt = 0; mt < 2; mt++) {
                int row = wbase + mt*16 + (lane & 15) + tx;
                int cblk = ks*2 + (lane >> 4);
                uint32_t aaddr = sAu + ds*33280 + row*256 + (uint32_t)((cblk ^ (row & 7)) << 4);
                asm volatile("ldmatrix.sync.aligned.m8n8.x4.shared.b16 {%0,%1,%2,%3}, [%4];"
                             : "=r"(a0[mt]), "=r"(a1[mt]), "=r"(a2[mt]), "=r"(a3[mt]) : "r"(aaddr));
            }
            #pragma unroll
            for (int nt = 0; nt < 8; nt++) {
                int n = nt*8 + (lane & 7);
                int cb = ks*2 + ((lane >> 3) & 1);
                uint32_t baddr = sBu + n*256 + (uint32_t)((cb ^ (n & 7)) << 4);
                uint32_t b0, b1;
                asm volatile("ldmatrix.sync.aligned.m8n8.x2.shared.b16 {%0,%1}, [%2];"
                             : "=r"(b0), "=r"(b1) : "r"(baddr));
                #pragma unroll
                for (int mt = 0; mt < 2; mt++)
                    asm volatile("mma.sync.aligned.m16n8k16.row.col.f32.f16.f16.f32 "
                                 "{%0,%1,%2,%3}, {%4,%5,%6,%7}, {%8,%9}, {%0,%1,%2,%3};"
                                 : "+f"(acc[mt][nt][0]), "+f"(acc[mt][nt][1]),
                                   "+f"(acc[mt][nt][2]), "+f"(acc[mt][nt][3])
                                 : "r"(a0[mt]), "r"(a1[mt]), "r"(a2[mt]), "r"(a3[mt]),
                                   "r"(b0), "r"(b1));
            }
        }
    }
    int g = lane >> 2, tq = lane & 3;
    #pragma unroll
    for (int mt = 0; mt < 2; mt++) {
        float* ob = g_fused + (size_t)bl * (C_*SW_) + (s0 + s_row)*W_ + wbase + mt*16 + g;
        #pragma unroll
        for (int nt = 0; nt < 8; nt++) {
            int o0 = nt*8 + 2*tq;
            ob[(size_t)o0*SW_]           = acc[mt][nt][0];
            ob[(size_t)(o0 + 1)*SW_]     = acc[mt][nt][1];
            ob[(size_t)o0*SW_ + 8]       = acc[mt][nt][2];
            ob[(size_t)(o0 + 1)*SW_ + 8] = acc[mt][nt][3];
        }
    }
}

// ---------------- K9: LayerNorm (+ bias field) + residual ----------------
__global__ void k_ln(const float* __restrict__ x, const float* __restrict__ lng,
                     const float* __restrict__ lnb, float* __restrict__ out) {
    __shared__ float sbuf1[8], sbuf2[8];
    __shared__ float s_mu, s_rstd;
    int blc = blockIdx.x, tid = threadIdx.x;
    int o = blc % C_;
    const float* fp = g_fused + (size_t)blc * SW_;
    const float* bp = g_bias + (size_t)o * SW_;
    float v[32];
    float sum = 0.f, sq = 0.f;
    #pragma unroll
    for (int k = 0; k < 32; k++) {
        int i = tid + 256*k;
        float t = fp[i] + bp[i];
        v[k] = t; sum += t; sq += t*t;
    }
    float ts = blockReduceSum(sum, sbuf1);
    __syncthreads();
    float tq = blockReduceSum(sq, sbuf2);
    if (tid == 0) {
        float mu = ts * (1.f / (float)SW_);
        float var = tq * (1.f / (float)SW_) - mu*mu;
        s_mu = mu;
        s_rstd = rsqrtf(var + 1e-5f);
    }
    __syncthreads();
    float mu = s_mu, rstd = s_rstd;
    const float* xp = x + (size_t)blc * SW_;
    float* op = out + (size_t)blc * SW_;
    #pragma unroll
    for (int k = 0; k < 32; k++) {
        int i = tid + 256*k;
        op[i] = (v[k] - mu) * rstd * lng[i] + lnb[i] + xp[i];
    }
}

// ---------------- launch ----------------
extern "C" void kernel_launch(void* const* d_in, const int* in_sizes, int n_in,
                              void* d_out, int out_size) {
    const float* x         = (const float*)d_in[0];
    const float* nu_log    = (const float*)d_in[1];
    const float* theta_log = (const float*)d_in[2];
    const float* disp_nu   = (const float*)d_in[3];
    const float* disp_th   = (const float*)d_in[4];
    const float* mlp_w1    = (const float*)d_in[5];
    const float* mlp_b1    = (const float*)d_in[6];
    const float* mlp_w2    = (const float*)d_in[7];
    const float* mlp_b2    = (const float*)d_in[8];
    const float* fscale    = (const float*)d_in[9];
    const float* U_row_r   = (const float*)d_in[10];
    const float* U_row_i   = (const float*)d_in[11];
    const float* V_col_r   = (const float*)d_in[12];
    const float* V_col_i   = (const float*)d_in[13];
    const float* proj_W_r  = (const float*)d_in[14];
    const float* proj_W_i  = (const float*)d_in[15];
    const float* proj_b_r  = (const float*)d_in[16];
    const float* proj_b_i  = (const float*)d_in[17];
    const float* convr_k   = (const float*)d_in[18];
    const float* convr_b   = (const float*)d_in[19];
    const float* convi_k   = (const float*)d_in[20];
    const float* convi_b   = (const float*)d_in[21];
    const float* fuse_k    = (const float*)d_in[22];
    const float* fuse_b    = (const float*)d_in[23];
    const float* ln_g      = (const float*)d_in[24];
    const float* ln_b      = (const float*)d_in[25];
    float* out = (float*)d_out;

    cudaFuncSetAttribute(k_u_mma,    cudaFuncAttributeMaxDynamicSharedMemorySize, SMEM_U_BYTES);
    cudaFuncSetAttribute(k_conv_mma, cudaFuncAttributeMaxDynamicSharedMemorySize, CONV_SMEM);

    k_poles<<<(CR_ + 255)/256, 256>>>(nu_log, theta_log, disp_nu, disp_th);
    k_pq<<<C_, 576>>>(fuse_k, convr_k, convi_k, convr_b, convi_b, fuse_b);
    k_ab<<<C_, 576>>>(proj_W_r, proj_W_i, proj_b_r, proj_b_i);
    k_bprep<<<72, 256>>>();
    k_bias<<<C_, 256>>>();
    k_u_mma<<<PLANES_, 256, SMEM_U_BYTES>>>(x, U_row_r, U_row_i, V_col_r, V_col_i);
    k_mlp<<<BL_, 256>>>(mlp_w1, mlp_b1, mlp_w2, mlp_b2, fscale);
    k_scan<<<16, 256>>>();
    k_recon_mma<<<PLANES_, 256>>>(U_row_r, U_row_i, V_col_r, V_col_i);
    k_conv_mma<<<512, 512, CONV_SMEM>>>();
    k_ln<<<PLANES_, 256>>>(x, ln_g, ln_b, out);
}

// round 9
// speedup vs baseline: 8.6626x; 1.0351x over previous
#include <cuda_runtime.h>
#include <cuda_fp16.h>
#include <math.h>
#include <stdint.h>

#define B_  2
#define L_  16
#define C_  64
#define S_  64
#define W_  128
#define R_  32
#define H_  32
#define BL_ (B_*L_)
#define SW_ (S_*W_)
#define CR_ (C_*R_)
#define PLANES_ (BL_*C_)
#define NELEM_ (PLANES_*SW_)

// ---------------- device scratch ----------------
__device__ float    g_ctx[BL_*C_];
__device__ float    g_mod_re[BL_*CR_], g_mod_im[BL_*CR_];
__device__ float    g_u_re[BL_*CR_],  g_u_im[BL_*CR_];
__device__ float    g_h_re[BL_*CR_],  g_h_im[BL_*CR_];
__device__ uint32_t g_yh[NELEM_];       // half2 (re,im) planes
__device__ uint32_t g_fh[NELEM_/2];     // half2 (o, o+1) fused planes
__device__ __half   g_Bw[9*8192];       // per-tap swizzled [o=64][k=128] fp16 weights
__device__ float    g_bias[C_*SW_];     // bias + border-tap field

// ---------------- helpers ----------------
__device__ __forceinline__ float blockReduceSum(float v, float* sbuf) {
    int lane = threadIdx.x & 31, warp = threadIdx.x >> 5;
    #pragma unroll
    for (int o = 16; o > 0; o >>= 1) v += __shfl_down_sync(0xffffffffu, v, o);
    if (lane == 0) sbuf[warp] = v;
    __syncthreads();
    int nw = blockDim.x >> 5;
    v = (threadIdx.x < nw) ? sbuf[threadIdx.x] : 0.f;
    if (warp == 0) {
        #pragma unroll
        for (int o = 16; o > 0; o >>= 1) v += __shfl_down_sync(0xffffffffu, v, o);
    }
    return v;
}
__device__ __forceinline__ uint32_t smem_u32(const void* p) {
    uint32_t a;
    asm("{ .reg .u64 t; cvta.to.shared.u64 t, %1; cvt.u32.u64 %0, t; }" : "=r"(a) : "l"(p));
    return a;
}

// ---------------- K0: merged prep (P/Q -> A/B -> Bw pack, T/c0 -> bias field) ----------------
// grid 64 (o), block 576 (cp*9+t)
__global__ void k_prep(const float* __restrict__ fuse_k, const float* __restrict__ convr_k,
                       const float* __restrict__ convi_k, const float* __restrict__ convr_b,
                       const float* __restrict__ convi_b, const float* __restrict__ fuse_b,
                       const float* __restrict__ Wr, const float* __restrict__ Wi,
                       const float* __restrict__ br, const float* __restrict__ bi) {
    int o = blockIdx.x, tid = threadIdx.x;
    __shared__ float sF1[C_], sF2[C_];
    __shared__ float sP[576], sQ[576], sA2[576], sB2[576];
    __shared__ float sT[9], sc0;
    if (tid < 64)       sF1[tid]      = fuse_k[o*128 + tid];
    else if (tid < 128) sF2[tid - 64] = fuse_k[o*128 + tid];
    __syncthreads();
    float p = 0.f, q = 0.f;
    for (int m = 0; m < C_; m++) {
        p += sF1[m] * convr_k[m*576 + tid];
        q += sF2[m] * convi_k[m*576 + tid];
    }
    sP[tid] = p; sQ[tid] = q;
    if (tid == 0) {
        float v = fuse_b[o];
        for (int m = 0; m < C_; m++) v += sF1[m]*convr_b[m] + sF2[m]*convi_b[m];
        sc0 = v;
    }
    __syncthreads();
    int cp = tid / 9, t = tid % 9;
    float a = 0.f, bb = 0.f;
    for (int cc = 0; cc < C_; cc++) {
        float pp = sP[cc*9 + t], qq = sQ[cc*9 + t];
        float wr = Wr[cc*C_ + cp], wi = Wi[cc*C_ + cp];
        a  += pp * wr + qq * wi;
        bb += -pp * wi + qq * wr;
    }
    sA2[tid] = a; sB2[tid] = bb;
    if (tid < 9) {
        float tt = 0.f;
        for (int cc = 0; cc < C_; cc++)
            tt += sP[cc*9 + tid]*br[cc] + sQ[cc*9 + tid]*bi[cc];
        sT[tid] = tt;
    }
    __syncthreads();
    // pack Bw for this o across 9 taps
    for (int i = tid; i < 9*128; i += 576) {
        int tt = i >> 7, k = i & 127;
        int ci = k >> 1, reim = k & 1;
        float wv = reim ? sB2[ci*9 + tt] : sA2[ci*9 + tt];
        int chunk = k >> 3;
        g_Bw[tt*8192 + o*128 + ((chunk ^ (o & 7)) << 3) + (k & 7)] = __float2half(wv);
    }
    // bias + border-tap field
    float T[9];
    #pragma unroll
    for (int k = 0; k < 9; k++) T[k] = sT[k];
    float c0 = sc0;
    for (int i = tid; i < SW_; i += 576) {
        int s = i >> 7, w = i & 127;
        float b = c0;
        #pragma unroll
        for (int k = 0; k < 9; k++) {
            int ds = k/3 - 1, dw = k%3 - 1;
            if (((unsigned)(s + ds) < (unsigned)S_) && ((unsigned)(w + dw) < (unsigned)W_))
                b += T[k];
        }
        g_bias[o*SW_ + i] = b;
    }
}

// ---------------- K3: MLP (gamma inlined) ----------------
__global__ void k_mlp(const float* __restrict__ w1, const float* __restrict__ b1,
                      const float* __restrict__ w2, const float* __restrict__ b2,
                      const float* __restrict__ fscale,
                      const float* __restrict__ nu_log, const float* __restrict__ dnu) {
    __shared__ float sc[C_], shid[H_], sf[CR_*2];
    int bl = blockIdx.x, tid = threadIdx.x;
    if (tid < C_) sc[tid] = g_ctx[bl*C_ + tid];
    __syncthreads();
    if (tid < H_) {
        float v = b1[tid];
        for (int cc = 0; cc < C_; cc++) v += sc[cc] * w1[cc*H_ + tid];
        shid[tid] = tanhf(v);
    }
    __syncthreads();
    for (int k = tid; k < CR_*2; k += 256) {
        float v = b2[k];
        #pragma unroll
        for (int j = 0; j < H_; j++) v += shid[j] * w2[j*(CR_*2) + k];
        sf[k] = v;
    }
    __syncthreads();
    float fs = *fscale;
    for (int cr = tid; cr < CR_; cr += 256) {
        float nu = expf(nu_log[cr] + dnu[cr]);
        float el = expf(-nu);
        float ga = sqrtf(fmaxf(1.f - el*el, 1e-6f));
        g_mod_re[bl*CR_ + cr] = ga * (1.f + fs * sf[2*cr]);
        g_mod_im[bl*CR_ + cr] = ga * (fs * sf[2*cr + 1]);
    }
}

// ---------------- K4: low-rank projection via mma.sync + ctx ----------------
#define SMEM_U_BYTES (16384 + 8192 + 32768 + 2048)
__global__ void __launch_bounds__(256) k_u_mma(const float* __restrict__ x,
        const float* __restrict__ Ur, const float* __restrict__ Ui,
        const float* __restrict__ Vr, const float* __restrict__ Vi) {
    extern __shared__ __align__(16) char smu[];
    __half* sXT = (__half*)smu;
    __half* sUp = (__half*)(smu + 16384);
    float*  sV  = (float*)(smu + 16384 + 8192);
    float*  sred = (float*)(smu + 16384 + 8192 + 32768);
    int tid = threadIdx.x, lane = tid & 31, warp = tid >> 5;
    int blc = blockIdx.x, c = blc & 63;

    const float* xp = x + (size_t)blc * SW_;
    float csum = 0.f;
    for (int i = tid; i < SW_; i += 256) {
        int s = i >> 7, w = i & 127;
        float xv = xp[i];
        csum += xv;
        int off = w*128 + ((((s >> 3) ^ (w & 7))) << 4) + (s & 7)*2;
        *(__half*)((char*)sXT + off) = __float2half(xv);
    }
    for (int i = tid; i < 64*64; i += 256) {
        int n = i >> 6, k = i & 63;
        int r = n >> 1;
        float v = Ur[c*2048 + k*32 + r];
        if (n & 1) v = -Ui[c*2048 + k*32 + r];
        int off = n*128 + ((((k >> 3) ^ (n & 7))) << 4) + (k & 7)*2;
        *(__half*)((char*)sUp + off) = __float2half(v);
    }
    for (int i = tid; i < W_*R_; i += 256) {
        sV[i*2]     = Vr[c*4096 + i];
        sV[i*2 + 1] = Vi[c*4096 + i];
    }
    csum = blockReduceSum(csum, sred);
    if (tid == 0) g_ctx[blc] = csum * (1.f / (float)SW_);
    __syncthreads();

    uint32_t sXu = smem_u32(sXT), sUu = smem_u32(sUp);
    int wbase = warp * 16;
    float acc[8][4];
    #pragma unroll
    for (int nt = 0; nt < 8; nt++)
        #pragma unroll
        for (int j = 0; j < 4; j++) acc[nt][j] = 0.f;

    #pragma unroll
    for (int ks = 0; ks < 4; ks++) {
        int row = wbase + (lane & 15);
        int cblk = ks*2 + (lane >> 4);
        uint32_t aaddr = sXu + row*128 + (uint32_t)((cblk ^ (row & 7)) << 4);
        uint32_t a0, a1, a2, a3;
        asm volatile("ldmatrix.sync.aligned.m8n8.x4.shared.b16 {%0,%1,%2,%3}, [%4];"
                     : "=r"(a0), "=r"(a1), "=r"(a2), "=r"(a3) : "r"(aaddr));
        #pragma unroll
        for (int nt = 0; nt < 8; nt++) {
            int n = nt*8 + (lane & 7);
            int cb = ks*2 + ((lane >> 3) & 1);
            uint32_t baddr = sUu + n*128 + (uint32_t)((cb ^ (n & 7)) << 4);
            uint32_t b0, b1;
            asm volatile("ldmatrix.sync.aligned.m8n8.x2.shared.b16 {%0,%1}, [%2];"
                         : "=r"(b0), "=r"(b1) : "r"(baddr));
            asm volatile("mma.sync.aligned.m16n8k16.row.col.f32.f16.f16.f32 "
                         "{%0,%1,%2,%3}, {%4,%5,%6,%7}, {%8,%9}, {%0,%1,%2,%3};"
                         : "+f"(acc[nt][0]), "+f"(acc[nt][1]), "+f"(acc[nt][2]), "+f"(acc[nt][3])
                         : "r"(a0), "r"(a1), "r"(a2), "r"(a3), "r"(b0), "r"(b1));
        }
    }
    int g = lane >> 2, tq = lane & 3;
    float pre[8], pim[8];
    #pragma unroll
    for (int nt = 0; nt < 8; nt++) { pre[nt] = 0.f; pim[nt] = 0.f; }
    {
        int w1 = wbase + g, w2 = w1 + 8;
        #pragma unroll
        for (int nt = 0; nt < 8; nt++) {
            int r = nt*4 + tq;
            float vr1 = sV[(w1*32 + r)*2], vi1 = sV[(w1*32 + r)*2 + 1];
            float vr2 = sV[(w2*32 + r)*2], vi2 = sV[(w2*32 + r)*2 + 1];
            float ar = acc[nt][0], ai = acc[nt][1];
            float br = acc[nt][2], bi = acc[nt][3];
            pre[nt] += ar*vr1 + ai*vi1 + br*vr2 + bi*vi2;
            pim[nt] += ai*vr1 - ar*vi1 + bi*vr2 - br*vi2;
        }
    }
    #pragma unroll
    for (int nt = 0; nt < 8; nt++) {
        #pragma unroll
        for (int o = 16; o >= 4; o >>= 1) {
            pre[nt] += __shfl_down_sync(0xffffffffu, pre[nt], o);
            pim[nt] += __shfl_down_sync(0xffffffffu, pim[nt], o);
        }
    }
    __syncthreads();
    if (lane < 4) {
        #pragma unroll
        for (int nt = 0; nt < 8; nt++) {
            int r = nt*4 + lane;
            sred[warp*64 + r*2]     = pre[nt];
            sred[warp*64 + r*2 + 1] = pim[nt];
        }
    }
    __syncthreads();
    if (tid < 32) {
        int r = tid;
        float ur = 0.f, ui = 0.f;
        #pragma unroll
        for (int wp = 0; wp < 8; wp++) {
            ur += sred[wp*64 + r*2];
            ui += sred[wp*64 + r*2 + 1];
        }
        g_u_re[blc*R_ + r] = ur;
        g_u_im[blc*R_ + r] = ui;
    }
}

// ---------------- K5: scan (lam inlined, applies modulation) ----------------
__global__ void k_scan(const float* __restrict__ nu_log, const float* __restrict__ th_log,
                       const float* __restrict__ dnu, const float* __restrict__ dth) {
    int t = blockIdx.x * 256 + threadIdx.x;
    int b = t >> 11;
    int cr = t & (CR_ - 1);
    float nu = expf(nu_log[cr] + dnu[cr]);
    float th = expf(th_log[cr] + dth[cr]);
    float el = expf(-nu);
    float lr = el * cosf(th), li = el * sinf(th);
    float hr = 0.f, hi = 0.f;
    #pragma unroll
    for (int l = 0; l < L_; l++) {
        int idx = (b*L_ + l)*CR_ + cr;
        float ur_raw = g_u_re[idx], ui_raw = g_u_im[idx];
        float mr = g_mod_re[idx], mi = g_mod_im[idx];
        float ur = mr*ur_raw - mi*ui_raw;
        float ui = mr*ui_raw + mi*ur_raw;
        float nr = lr*hr - li*hi + ur;
        float ni = lr*hi + li*hr + ui;
        hr = nr; hi = ni;
        g_h_re[idx] = hr;
        g_h_im[idx] = hi;
    }
}

// ---------------- K6: reconstruct via mma.sync -> half2 planes ----------------
__global__ void __launch_bounds__(256) k_recon_mma(
        const float* __restrict__ Ur, const float* __restrict__ Ui,
        const float* __restrict__ Vr, const float* __restrict__ Vi) {
    __shared__ __align__(16) __half sA[64*64];
    __shared__ __align__(16) __half sBv[256*64];
    __shared__ float sh[64];
    int tid = threadIdx.x, lane = tid & 31, warp = tid >> 5;
    int blc = blockIdx.x, c = blc & 63;
    if (tid < 64) sh[tid] = (tid < 32) ? g_h_re[blc*R_ + tid] : g_h_im[blc*R_ + tid - 32];
    __syncthreads();
    for (int i = tid; i < 2048; i += 256) {
        int s = i >> 5, r = i & 31;
        float hr = sh[r], hi = sh[32 + r];
        float ur = Ur[c*2048 + s*32 + r], ui = Ui[c*2048 + s*32 + r];
        float gr = hr*ur - hi*ui;
        float gi = hr*ui + hi*ur;
        int off = s*128 + ((((r >> 2) ^ (s & 7))) << 4) + (r & 3)*4;
        __half2 h2 = __floats2half2_rn(gr, gi);
        *(uint32_t*)((char*)sA + off) = *(uint32_t*)&h2;
    }
    for (int i = tid; i < 256*64; i += 256) {
        int n = i >> 6, k = i & 63;
        int w = n >> 1, nc = n & 1, r = k >> 1, kc = k & 1;
        float vr = Vr[c*4096 + w*32 + r], vi = Vi[c*4096 + w*32 + r];
        float v = nc ? (kc ? vr : vi) : (kc ? -vi : vr);
        int off = n*128 + ((((k >> 3) ^ (n & 7))) << 4) + (k & 7)*2;
        *(__half*)((char*)sBv + off) = __float2half(v);
    }
    __syncthreads();

    uint32_t sAu = smem_u32(sA), sBu = smem_u32(sBv);
    int mt = warp & 3, nh = warp >> 2;
    int mrow = mt * 16;
    float acc[16][4];
    #pragma unroll
    for (int nt = 0; nt < 16; nt++)
        #pragma unroll
        for (int j = 0; j < 4; j++) acc[nt][j] = 0.f;

    #pragma unroll
    for (int ks = 0; ks < 4; ks++) {
        int row = mrow + (lane & 15);
        int cblk = ks*2 + (lane >> 4);
        uint32_t aaddr = sAu + row*128 + (uint32_t)((cblk ^ (row & 7)) << 4);
        uint32_t a0, a1, a2, a3;
        asm volatile("ldmatrix.sync.aligned.m8n8.x4.shared.b16 {%0,%1,%2,%3}, [%4];"
                     : "=r"(a0), "=r"(a1), "=r"(a2), "=r"(a3) : "r"(aaddr));
        #pragma unroll
        for (int nt = 0; nt < 16; nt++) {
            int n = (nh*16 + nt)*8 + (lane & 7);
            int cb = ks*2 + ((lane >> 3) & 1);
            uint32_t baddr = sBu + n*128 + (uint32_t)((cb ^ (n & 7)) << 4);
            uint32_t b0, b1;
            asm volatile("ldmatrix.sync.aligned.m8n8.x2.shared.b16 {%0,%1}, [%2];"
                         : "=r"(b0), "=r"(b1) : "r"(baddr));
            asm volatile("mma.sync.aligned.m16n8k16.row.col.f32.f16.f16.f32 "
                         "{%0,%1,%2,%3}, {%4,%5,%6,%7}, {%8,%9}, {%0,%1,%2,%3};"
                         : "+f"(acc[nt][0]), "+f"(acc[nt][1]), "+f"(acc[nt][2]), "+f"(acc[nt][3])
                         : "r"(a0), "r"(a1), "r"(a2), "r"(a3), "r"(b0), "r"(b1));
        }
    }
    int g = lane >> 2, tq = lane & 3;
    uint32_t* py = g_yh + (size_t)blc*SW_;
    #pragma unroll
    for (int nt = 0; nt < 16; nt++) {
        int w = (nh*16 + nt)*4 + tq;
        __half2 h1 = __floats2half2_rn(acc[nt][0], acc[nt][1]);
        __half2 h2 = __floats2half2_rn(acc[nt][2], acc[nt][3]);
        py[(mrow + g)*W_ + w]     = *(uint32_t*)&h1;
        py[(mrow + g + 8)*W_ + w] = *(uint32_t*)&h2;
    }
}

// ---------------- K8: fp16 mma.sync conv-GEMM, 4 s-rows per CTA ----------------
#define CONV_SMEM (199680 + 16384)
__global__ void __launch_bounds__(512) k_conv_mma() {
    extern __shared__ __align__(16) char smc[];
    char* sB = smc + 199680;
    int tid = threadIdx.x, lane = tid & 31, warp = tid >> 5;
    int bl = blockIdx.x >> 4, s0 = (blockIdx.x & 15) * 4;

    const uint32_t* ybl = g_yh + (size_t)bl * (C_*SW_);
    for (int i = tid; i < 6*130*64; i += 512) {
        int ci = i / 780, rem = i % 780;
        int ds = rem / 130, pw = rem % 130;
        int sr = s0 + ds - 1, w = pw - 1;
        uint32_t v = 0u;
        if (((unsigned)sr < (unsigned)S_) && ((unsigned)w < (unsigned)W_))
            v = ybl[(size_t)ci*SW_ + sr*W_ + w];
        int phys = ds*33280 + pw*256 + ((((ci >> 2) ^ (pw & 7))) << 4) + (ci & 3)*4;
        *(uint32_t*)(smc + phys) = v;
    }

    float acc[2][8][4];
    #pragma unroll
    for (int mt = 0; mt < 2; mt++)
        #pragma unroll
        for (int nt = 0; nt < 8; nt++)
            #pragma unroll
            for (int j = 0; j < 4; j++) acc[mt][nt][j] = 0.f;

    uint32_t sAu = smem_u32(smc), sBu = smem_u32(sB);
    int s_row = warp >> 2;
    int wbase = (warp & 3) * 32;

    #pragma unroll 1
    for (int t = 0; t < 9; t++) {
        __syncthreads();
        {
            const uint4* src = (const uint4*)(g_Bw + t*8192);
            uint4* dst = (uint4*)sB;
            dst[tid]       = src[tid];
            dst[tid + 512] = src[tid + 512];
        }
        __syncthreads();
        int tx = t % 3, ds = s_row + t / 3;
        #pragma unroll 1
        for (int ks = 0; ks < 8; ks++) {
            uint32_t a0[2], a1[2], a2[2], a3[2];
            #pragma unroll
            for (int mt = 0; mt < 2; mt++) {
                int row = wbase + mt*16 + (lane & 15) + tx;
                int cblk = ks*2 + (lane >> 4);
                uint32_t aaddr = sAu + ds*33280 + row*256 + (uint32_t)((cblk ^ (row & 7)) << 4);
                asm volatile("ldmatrix.sync.aligned.m8n8.x4.shared.b16 {%0,%1,%2,%3}, [%4];"
                             : "=r"(a0[mt]), "=r"(a1[mt]), "=r"(a2[mt]), "=r"(a3[mt]) : "r"(aaddr));
            }
            #pragma unroll
            for (int nt = 0; nt < 8; nt++) {
                int n = nt*8 + (lane & 7);
                int cb = ks*2 + ((lane >> 3) & 1);
                uint32_t baddr = sBu + n*256 + (uint32_t)((cb ^ (n & 7)) << 4);
                uint32_t b0, b1;
                asm volatile("ldmatrix.sync.aligned.m8n8.x2.shared.b16 {%0,%1}, [%2];"
                             : "=r"(b0), "=r"(b1) : "r"(baddr));
                #pragma unroll
                for (int mt = 0; mt < 2; mt++)
                    asm volatile("mma.sync.aligned.m16n8k16.row.col.f32.f16.f16.f32 "
                                 "{%0,%1,%2,%3}, {%4,%5,%6,%7}, {%8,%9}, {%0,%1,%2,%3};"
                                 : "+f"(acc[mt][nt][0]), "+f"(acc[mt][nt][1]),
                                   "+f"(acc[mt][nt][2]), "+f"(acc[mt][nt][3])
                                 : "r"(a0[mt]), "r"(a1[mt]), "r"(a2[mt]), "r"(a3[mt]),
                                   "r"(b0), "r"(b1));
            }
        }
    }
    // epilogue: pack (o, o+1) half2 pairs -> g_fh
    int g = lane >> 2, tq = lane & 3;
    #pragma unroll
    for (int mt = 0; mt < 2; mt++) {
        uint32_t* ob = g_fh + (size_t)bl * (32*SW_) + (s0 + s_row)*W_ + wbase + mt*16 + g;
        #pragma unroll
        for (int nt = 0; nt < 8; nt++) {
            int pi = nt*4 + tq;   // o-pair index = (nt*8 + 2tq)/2
            __half2 hA = __floats2half2_rn(acc[mt][nt][0], acc[mt][nt][1]);
            __half2 hB = __floats2half2_rn(acc[mt][nt][2], acc[mt][nt][3]);
            ob[(size_t)pi*SW_]     = *(uint32_t*)&hA;
            ob[(size_t)pi*SW_ + 8] = *(uint32_t*)&hB;
        }
    }
}

// ---------------- K9: LayerNorm over o-pairs (+ bias) + residual ----------------
// grid 1024 = bl*32 + o-pair; 512 threads
__global__ void __launch_bounds__(512) k_ln(const float* __restrict__ x,
                     const float* __restrict__ lng,
                     const float* __restrict__ lnb, float* __restrict__ out) {
    __shared__ float sbuf1[16], sbuf2[16];
    __shared__ float s_mu0, s_r0, s_mu1, s_r1;
    int blc2 = blockIdx.x, tid = threadIdx.x;
    int bl = blc2 >> 5, op = blc2 & 31;
    int o0 = op * 2;
    const uint32_t* fp = g_fh + (size_t)blc2 * SW_;
    const float* bp0 = g_bias + (size_t)o0 * SW_;
    const float* bp1 = g_bias + (size_t)(o0 + 1) * SW_;
    float v0[16], v1[16];
    float sum0 = 0.f, sq0 = 0.f, sum1 = 0.f, sq1 = 0.f;
    #pragma unroll
    for (int k = 0; k < 16; k++) {
        int i = tid + 512*k;
        uint32_t u = fp[i];
        __half2 h = *(__half2*)&u;
        float2 f = __half22float2(h);
        float t0 = f.x + bp0[i];
        float t1 = f.y + bp1[i];
        v0[k] = t0; v1[k] = t1;
        sum0 += t0; sq0 += t0*t0;
        sum1 += t1; sq1 += t1*t1;
    }
    float ts0 = blockReduceSum(sum0, sbuf1);
    __syncthreads();
    float tq0 = blockReduceSum(sq0, sbuf2);
    __syncthreads();
    float ts1 = blockReduceSum(sum1, sbuf1);
    __syncthreads();
    float tq1 = blockReduceSum(sq1, sbuf2);
    if (tid == 0) {
        float mu0 = ts0 * (1.f / (float)SW_);
        float var0 = tq0 * (1.f / (float)SW_) - mu0*mu0;
        s_mu0 = mu0; s_r0 = rsqrtf(var0 + 1e-5f);
        float mu1 = ts1 * (1.f / (float)SW_);
        float var1 = tq1 * (1.f / (float)SW_) - mu1*mu1;
        s_mu1 = mu1; s_r1 = rsqrtf(var1 + 1e-5f);
    }
    __syncthreads();
    float mu0 = s_mu0, r0 = s_r0, mu1 = s_mu1, r1 = s_r1;
    const float* xp0 = x + ((size_t)bl*C_ + o0)*SW_;
    const float* xp1 = xp0 + SW_;
    float* op0 = out + ((size_t)bl*C_ + o0)*SW_;
    float* op1 = op0 + SW_;
    #pragma unroll
    for (int k = 0; k < 16; k++) {
        int i = tid + 512*k;
        float gg = lng[i], bb = lnb[i];
        op0[i] = (v0[k] - mu0) * r0 * gg + bb + xp0[i];
        op1[i] = (v1[k] - mu1) * r1 * gg + bb + xp1[i];
    }
}

// ---------------- launch ----------------
extern "C" void kernel_launch(void* const* d_in, const int* in_sizes, int n_in,
                              void* d_out, int out_size) {
    const float* x         = (const float*)d_in[0];
    const float* nu_log    = (const float*)d_in[1];
    const float* theta_log = (const float*)d_in[2];
    const float* disp_nu   = (const float*)d_in[3];
    const float* disp_th   = (const float*)d_in[4];
    const float* mlp_w1    = (const float*)d_in[5];
    const float* mlp_b1    = (const float*)d_in[6];
    const float* mlp_w2    = (const float*)d_in[7];
    const float* mlp_b2    = (const float*)d_in[8];
    const float* fscale    = (const float*)d_in[9];
    const float* U_row_r   = (const float*)d_in[10];
    const float* U_row_i   = (const float*)d_in[11];
    const float* V_col_r   = (const float*)d_in[12];
    const float* V_col_i   = (const float*)d_in[13];
    const float* proj_W_r  = (const float*)d_in[14];
    const float* proj_W_i  = (const float*)d_in[15];
    const float* proj_b_r  = (const float*)d_in[16];
    const float* proj_b_i  = (const float*)d_in[17];
    const float* convr_k   = (const float*)d_in[18];
    const float* convr_b   = (const float*)d_in[19];
    const float* convi_k   = (const float*)d_in[20];
    const float* convi_b   = (const float*)d_in[21];
    const float* fuse_k    = (const float*)d_in[22];
    const float* fuse_b    = (const float*)d_in[23];
    const float* ln_g      = (const float*)d_in[24];
    const float* ln_b      = (const float*)d_in[25];
    float* out = (float*)d_out;

    cudaFuncSetAttribute(k_u_mma,    cudaFuncAttributeMaxDynamicSharedMemorySize, SMEM_U_BYTES);
    cudaFuncSetAttribute(k_conv_mma, cudaFuncAttributeMaxDynamicSharedMemorySize, CONV_SMEM);

    k_prep<<<C_, 576>>>(fuse_k, convr_k, convi_k, convr_b, convi_b, fuse_b,
                        proj_W_r, proj_W_i, proj_b_r, proj_b_i);
    k_u_mma<<<PLANES_, 256, SMEM_U_BYTES>>>(x, U_row_r, U_row_i, V_col_r, V_col_i);
    k_mlp<<<BL_, 256>>>(mlp_w1, mlp_b1, mlp_w2, mlp_b2, fscale, nu_log, disp_nu);
    k_scan<<<16, 256>>>(nu_log, theta_log, disp_nu, disp_th);
    k_recon_mma<<<PLANES_, 256>>>(U_row_r, U_row_i, V_col_r, V_col_i);
    k_conv_mma<<<512, 512, CONV_SMEM>>>();
    k_ln<<<1024, 512>>>(x, ln_g, ln_b, out);
}

// round 10
// speedup vs baseline: 10.2139x; 1.1791x over previous
#include <cuda_runtime.h>
#include <cuda_fp16.h>
#include <math.h>
#include <stdint.h>

#define B_  2
#define L_  16
#define C_  64
#define S_  64
#define W_  128
#define R_  32
#define H_  32
#define BL_ (B_*L_)
#define SW_ (S_*W_)
#define CR_ (C_*R_)
#define PLANES_ (BL_*C_)
#define NELEM_ (PLANES_*SW_)

// ---------------- device scratch ----------------
__device__ float    g_ctx[BL_*C_];
__device__ float    g_u_re[BL_*CR_],  g_u_im[BL_*CR_];
__device__ float    g_h_re[BL_*CR_],  g_h_im[BL_*CR_];
__device__ uint32_t g_yh[NELEM_];       // half2 (re,im) planes
__device__ uint32_t g_fh[NELEM_/2];     // half2 (o, o+1) fused planes
__device__ __half   g_Bw[9*8192];       // per-tap swizzled [o=64][k=128] fp16 weights
__device__ float    g_bias[C_*SW_];     // bias + border-tap field

// ---------------- helpers ----------------
__device__ __forceinline__ float blockReduceSum(float v, float* sbuf) {
    int lane = threadIdx.x & 31, warp = threadIdx.x >> 5;
    #pragma unroll
    for (int o = 16; o > 0; o >>= 1) v += __shfl_down_sync(0xffffffffu, v, o);
    if (lane == 0) sbuf[warp] = v;
    __syncthreads();
    int nw = blockDim.x >> 5;
    v = (threadIdx.x < nw) ? sbuf[threadIdx.x] : 0.f;
    if (warp == 0) {
        #pragma unroll
        for (int o = 16; o > 0; o >>= 1) v += __shfl_down_sync(0xffffffffu, v, o);
    }
    return v;
}
__device__ __forceinline__ uint32_t smem_u32(const void* p) {
    uint32_t a;
    asm("{ .reg .u64 t; cvta.to.shared.u64 t, %1; cvt.u32.u64 %0, t; }" : "=r"(a) : "l"(p));
    return a;
}

// ---------------- K4+K0: u-projection MMA (blocks 0..2047) + prep (blocks 2048..2111) ----------------
#define SMEM_U_BYTES (16384 + 8192 + 32768 + 2048)
__global__ void __launch_bounds__(256) k_u_prep(const float* __restrict__ x,
        const float* __restrict__ Ur, const float* __restrict__ Ui,
        const float* __restrict__ Vr, const float* __restrict__ Vi,
        const float* __restrict__ fuse_k, const float* __restrict__ convr_k,
        const float* __restrict__ convi_k, const float* __restrict__ convr_b,
        const float* __restrict__ convi_b, const float* __restrict__ fuse_b,
        const float* __restrict__ Wr, const float* __restrict__ Wi,
        const float* __restrict__ br, const float* __restrict__ bi) {
    extern __shared__ __align__(16) char smu[];
    int tid = threadIdx.x, lane = tid & 31, warp = tid >> 5;

    if (blockIdx.x >= 2048) {
        // ======== prep branch ========
        int o = blockIdx.x - 2048;
        float* sF1 = (float*)smu;           // 64
        float* sF2 = sF1 + 64;              // 64
        float* sP  = sF2 + 64;              // 576
        float* sQ  = sP + 576;              // 576
        float* sA2 = sQ + 576;              // 576
        float* sB2 = sA2 + 576;             // 576
        float* sT  = sB2 + 576;             // 9
        float* sc0 = sT + 9;                // 1
        if (tid < 64)       sF1[tid]      = fuse_k[o*128 + tid];
        else if (tid < 128) sF2[tid - 64] = fuse_k[o*128 + tid];
        __syncthreads();
        for (int idx = tid; idx < 576; idx += 256) {
            float p = 0.f, q = 0.f;
            for (int m = 0; m < C_; m++) {
                p += sF1[m] * convr_k[m*576 + idx];
                q += sF2[m] * convi_k[m*576 + idx];
            }
            sP[idx] = p; sQ[idx] = q;
        }
        if (tid == 0) {
            float v = fuse_b[o];
            for (int m = 0; m < C_; m++) v += sF1[m]*convr_b[m] + sF2[m]*convi_b[m];
            *sc0 = v;
        }
        __syncthreads();
        for (int idx = tid; idx < 576; idx += 256) {
            int cp = idx / 9, t = idx % 9;
            float a = 0.f, bb = 0.f;
            for (int cc = 0; cc < C_; cc++) {
                float pp = sP[cc*9 + t], qq = sQ[cc*9 + t];
                float wr = Wr[cc*C_ + cp], wi = Wi[cc*C_ + cp];
                a  += pp * wr + qq * wi;
                bb += -pp * wi + qq * wr;
            }
            sA2[idx] = a; sB2[idx] = bb;
        }
        if (tid < 9) {
            float tt = 0.f;
            for (int cc = 0; cc < C_; cc++)
                tt += sP[cc*9 + tid]*br[cc] + sQ[cc*9 + tid]*bi[cc];
            sT[tid] = tt;
        }
        __syncthreads();
        for (int i = tid; i < 9*128; i += 256) {
            int tt = i >> 7, k = i & 127;
            int ci = k >> 1, reim = k & 1;
            float wv = reim ? sB2[ci*9 + tt] : sA2[ci*9 + tt];
            int chunk = k >> 3;
            g_Bw[tt*8192 + o*128 + ((chunk ^ (o & 7)) << 3) + (k & 7)] = __float2half(wv);
        }
        float T[9];
        #pragma unroll
        for (int k = 0; k < 9; k++) T[k] = sT[k];
        float c0 = *sc0;
        for (int i = tid; i < SW_; i += 256) {
            int s = i >> 7, w = i & 127;
            float b = c0;
            #pragma unroll
            for (int k = 0; k < 9; k++) {
                int ds = k/3 - 1, dw = k%3 - 1;
                if (((unsigned)(s + ds) < (unsigned)S_) && ((unsigned)(w + dw) < (unsigned)W_))
                    b += T[k];
            }
            g_bias[o*SW_ + i] = b;
        }
        return;
    }

    // ======== u-projection branch ========
    __half* sXT = (__half*)smu;
    __half* sUp = (__half*)(smu + 16384);
    float*  sV  = (float*)(smu + 16384 + 8192);
    float*  sred = (float*)(smu + 16384 + 8192 + 32768);
    int blc = blockIdx.x, c = blc & 63;

    const float* xp = x + (size_t)blc * SW_;
    float csum = 0.f;
    for (int i = tid; i < SW_; i += 256) {
        int s = i >> 7, w = i & 127;
        float xv = xp[i];
        csum += xv;
        int off = w*128 + ((((s >> 3) ^ (w & 7))) << 4) + (s & 7)*2;
        *(__half*)((char*)sXT + off) = __float2half(xv);
    }
    for (int i = tid; i < 64*64; i += 256) {
        int n = i >> 6, k = i & 63;
        int r = n >> 1;
        float v = Ur[c*2048 + k*32 + r];
        if (n & 1) v = -Ui[c*2048 + k*32 + r];
        int off = n*128 + ((((k >> 3) ^ (n & 7))) << 4) + (k & 7)*2;
        *(__half*)((char*)sUp + off) = __float2half(v);
    }
    for (int i = tid; i < W_*R_; i += 256) {
        sV[i*2]     = Vr[c*4096 + i];
        sV[i*2 + 1] = Vi[c*4096 + i];
    }
    csum = blockReduceSum(csum, sred);
    if (tid == 0) g_ctx[blc] = csum * (1.f / (float)SW_);
    __syncthreads();

    uint32_t sXu = smem_u32(sXT), sUu = smem_u32(sUp);
    int wbase = warp * 16;
    float acc[8][4];
    #pragma unroll
    for (int nt = 0; nt < 8; nt++)
        #pragma unroll
        for (int j = 0; j < 4; j++) acc[nt][j] = 0.f;

    #pragma unroll
    for (int ks = 0; ks < 4; ks++) {
        int row = wbase + (lane & 15);
        int cblk = ks*2 + (lane >> 4);
        uint32_t aaddr = sXu + row*128 + (uint32_t)((cblk ^ (row & 7)) << 4);
        uint32_t a0, a1, a2, a3;
        asm volatile("ldmatrix.sync.aligned.m8n8.x4.shared.b16 {%0,%1,%2,%3}, [%4];"
                     : "=r"(a0), "=r"(a1), "=r"(a2), "=r"(a3) : "r"(aaddr));
        #pragma unroll
        for (int np = 0; np < 4; np++) {
            int n = (np*2 + (lane >> 4))*8 + (lane & 7);
            int cb = ks*2 + ((lane >> 3) & 1);
            uint32_t baddr = sUu + n*128 + (uint32_t)((cb ^ (n & 7)) << 4);
            uint32_t b0, b1, b2, b3;
            asm volatile("ldmatrix.sync.aligned.m8n8.x4.shared.b16 {%0,%1,%2,%3}, [%4];"
                         : "=r"(b0), "=r"(b1), "=r"(b2), "=r"(b3) : "r"(baddr));
            asm volatile("mma.sync.aligned.m16n8k16.row.col.f32.f16.f16.f32 "
                         "{%0,%1,%2,%3}, {%4,%5,%6,%7}, {%8,%9}, {%0,%1,%2,%3};"
                         : "+f"(acc[np*2][0]), "+f"(acc[np*2][1]), "+f"(acc[np*2][2]), "+f"(acc[np*2][3])
                         : "r"(a0), "r"(a1), "r"(a2), "r"(a3), "r"(b0), "r"(b1));
            asm volatile("mma.sync.aligned.m16n8k16.row.col.f32.f16.f16.f32 "
                         "{%0,%1,%2,%3}, {%4,%5,%6,%7}, {%8,%9}, {%0,%1,%2,%3};"
                         : "+f"(acc[np*2+1][0]), "+f"(acc[np*2+1][1]), "+f"(acc[np*2+1][2]), "+f"(acc[np*2+1][3])
                         : "r"(a0), "r"(a1), "r"(a2), "r"(a3), "r"(b2), "r"(b3));
        }
    }
    int g = lane >> 2, tq = lane & 3;
    float pre[8], pim[8];
    #pragma unroll
    for (int nt = 0; nt < 8; nt++) { pre[nt] = 0.f; pim[nt] = 0.f; }
    {
        int w1 = wbase + g, w2 = w1 + 8;
        #pragma unroll
        for (int nt = 0; nt < 8; nt++) {
            int r = nt*4 + tq;
            float vr1 = sV[(w1*32 + r)*2], vi1 = sV[(w1*32 + r)*2 + 1];
            float vr2 = sV[(w2*32 + r)*2], vi2 = sV[(w2*32 + r)*2 + 1];
            float ar = acc[nt][0], ai = acc[nt][1];
            float br2 = acc[nt][2], bi2 = acc[nt][3];
            pre[nt] += ar*vr1 + ai*vi1 + br2*vr2 + bi2*vi2;
            pim[nt] += ai*vr1 - ar*vi1 + bi2*vr2 - br2*vi2;
        }
    }
    #pragma unroll
    for (int nt = 0; nt < 8; nt++) {
        #pragma unroll
        for (int o = 16; o >= 4; o >>= 1) {
            pre[nt] += __shfl_down_sync(0xffffffffu, pre[nt], o);
            pim[nt] += __shfl_down_sync(0xffffffffu, pim[nt], o);
        }
    }
    __syncthreads();
    if (lane < 4) {
        #pragma unroll
        for (int nt = 0; nt < 8; nt++) {
            int r = nt*4 + lane;
            sred[warp*64 + r*2]     = pre[nt];
            sred[warp*64 + r*2 + 1] = pim[nt];
        }
    }
    __syncthreads();
    if (tid < 32) {
        int r = tid;
        float ur = 0.f, ui = 0.f;
        #pragma unroll
        for (int wp = 0; wp < 8; wp++) {
            ur += sred[wp*64 + r*2];
            ui += sred[wp*64 + r*2 + 1];
        }
        g_u_re[blc*R_ + r] = ur;
        g_u_im[blc*R_ + r] = ui;
    }
}

// ---------------- K5: fused MLP + modulation + scan ----------------
// grid 16 = (b<<3 | chunk); block 256; cr = chunk*256 + tid
__global__ void __launch_bounds__(256) k_scan(
        const float* __restrict__ nu_log, const float* __restrict__ th_log,
        const float* __restrict__ dnu, const float* __restrict__ dth,
        const float* __restrict__ w1, const float* __restrict__ b1,
        const float* __restrict__ w2, const float* __restrict__ b2,
        const float* __restrict__ fscale) {
    __shared__ float sctx[16*64];
    __shared__ float shid[16*32];
    int tid = threadIdx.x;
    int b = blockIdx.x >> 3, chunk = blockIdx.x & 7;
    int cr = chunk*256 + tid;

    for (int i = tid; i < 16*64; i += 256)
        sctx[i] = g_ctx[b*16*64 + i];
    __syncthreads();
    for (int idx = tid; idx < 512; idx += 256) {
        int l = idx >> 5, h = idx & 31;
        float v = b1[h];
        for (int cc = 0; cc < C_; cc++) v += sctx[l*64 + cc] * w1[cc*H_ + h];
        shid[l*32 + h] = tanhf(v);
    }
    __syncthreads();

    // per-thread: sf columns 2cr, 2cr+1 for all 16 l
    float fr[16], fi[16];
    float b2r = b2[2*cr], b2i = b2[2*cr + 1];
    #pragma unroll
    for (int l = 0; l < 16; l++) { fr[l] = b2r; fi[l] = b2i; }
    for (int j = 0; j < H_; j++) {
        float wr = w2[j*(CR_*2) + 2*cr];
        float wi = w2[j*(CR_*2) + 2*cr + 1];
        #pragma unroll
        for (int l = 0; l < 16; l++) {
            float hv = shid[l*32 + j];
            fr[l] = fmaf(hv, wr, fr[l]);
            fi[l] = fmaf(hv, wi, fi[l]);
        }
    }
    float fs = *fscale;
    float nu = expf(nu_log[cr] + dnu[cr]);
    float th = expf(th_log[cr] + dth[cr]);
    float el = expf(-nu);
    float ga = sqrtf(fmaxf(1.f - el*el, 1e-6f));
    float lr = el * cosf(th), li = el * sinf(th);
    float hr = 0.f, hi = 0.f;
    #pragma unroll
    for (int l = 0; l < L_; l++) {
        int idx = (b*L_ + l)*CR_ + cr;
        float mr = ga * (1.f + fs * fr[l]);
        float mi = ga * (fs * fi[l]);
        float ur_raw = g_u_re[idx], ui_raw = g_u_im[idx];
        float ur = mr*ur_raw - mi*ui_raw;
        float ui = mr*ui_raw + mi*ur_raw;
        float nr = lr*hr - li*hi + ur;
        float ni = lr*hi + li*hr + ui;
        hr = nr; hi = ni;
        g_h_re[idx] = hr;
        g_h_im[idx] = hi;
    }
}

// ---------------- K6: reconstruct via mma.sync -> half2 planes ----------------
__global__ void __launch_bounds__(256) k_recon_mma(
        const float* __restrict__ Ur, const float* __restrict__ Ui,
        const float* __restrict__ Vr, const float* __restrict__ Vi) {
    __shared__ __align__(16) __half sA[64*64];
    __shared__ __align__(16) __half sBv[256*64];
    __shared__ float sh[64];
    int tid = threadIdx.x, lane = tid & 31, warp = tid >> 5;
    int blc = blockIdx.x, c = blc & 63;
    if (tid < 64) sh[tid] = (tid < 32) ? g_h_re[blc*R_ + tid] : g_h_im[blc*R_ + tid - 32];
    __syncthreads();
    for (int i = tid; i < 2048; i += 256) {
        int s = i >> 5, r = i & 31;
        float hr = sh[r], hi = sh[32 + r];
        float ur = Ur[c*2048 + s*32 + r], ui = Ui[c*2048 + s*32 + r];
        float gr = hr*ur - hi*ui;
        float gi = hr*ui + hi*ur;
        int off = s*128 + ((((r >> 2) ^ (s & 7))) << 4) + (r & 3)*4;
        __half2 h2 = __floats2half2_rn(gr, gi);
        *(uint32_t*)((char*)sA + off) = *(uint32_t*)&h2;
    }
    for (int i = tid; i < 256*64; i += 256) {
        int n = i >> 6, k = i & 63;
        int w = n >> 1, nc = n & 1, r = k >> 1, kc = k & 1;
        float vr = Vr[c*4096 + w*32 + r], vi = Vi[c*4096 + w*32 + r];
        float v = nc ? (kc ? vr : vi) : (kc ? -vi : vr);
        int off = n*128 + ((((k >> 3) ^ (n & 7))) << 4) + (k & 7)*2;
        *(__half*)((char*)sBv + off) = __float2half(v);
    }
    __syncthreads();

    uint32_t sAu = smem_u32(sA), sBu = smem_u32(sBv);
    int mt = warp & 3, nh = warp >> 2;
    int mrow = mt * 16;
    float acc[16][4];
    #pragma unroll
    for (int nt = 0; nt < 16; nt++)
        #pragma unroll
        for (int j = 0; j < 4; j++) acc[nt][j] = 0.f;

    #pragma unroll
    for (int ks = 0; ks < 4; ks++) {
        int row = mrow + (lane & 15);
        int cblk = ks*2 + (lane >> 4);
        uint32_t aaddr = sAu + row*128 + (uint32_t)((cblk ^ (row & 7)) << 4);
        uint32_t a0, a1, a2, a3;
        asm volatile("ldmatrix.sync.aligned.m8n8.x4.shared.b16 {%0,%1,%2,%3}, [%4];"
                     : "=r"(a0), "=r"(a1), "=r"(a2), "=r"(a3) : "r"(aaddr));
        #pragma unroll
        for (int np = 0; np < 8; np++) {
            int n = (nh*16 + np*2 + (lane >> 4))*8 + (lane & 7);
            int cb = ks*2 + ((lane >> 3) & 1);
            uint32_t baddr = sBu + n*128 + (uint32_t)((cb ^ (n & 7)) << 4);
            uint32_t b0, b1, b2, b3;
            asm volatile("ldmatrix.sync.aligned.m8n8.x4.shared.b16 {%0,%1,%2,%3}, [%4];"
                         : "=r"(b0), "=r"(b1), "=r"(b2), "=r"(b3) : "r"(baddr));
            asm volatile("mma.sync.aligned.m16n8k16.row.col.f32.f16.f16.f32 "
                         "{%0,%1,%2,%3}, {%4,%5,%6,%7}, {%8,%9}, {%0,%1,%2,%3};"
                         : "+f"(acc[np*2][0]), "+f"(acc[np*2][1]), "+f"(acc[np*2][2]), "+f"(acc[np*2][3])
                         : "r"(a0), "r"(a1), "r"(a2), "r"(a3), "r"(b0), "r"(b1));
            asm volatile("mma.sync.aligned.m16n8k16.row.col.f32.f16.f16.f32 "
                         "{%0,%1,%2,%3}, {%4,%5,%6,%7}, {%8,%9}, {%0,%1,%2,%3};"
                         : "+f"(acc[np*2+1][0]), "+f"(acc[np*2+1][1]), "+f"(acc[np*2+1][2]), "+f"(acc[np*2+1][3])
                         : "r"(a0), "r"(a1), "r"(a2), "r"(a3), "r"(b2), "r"(b3));
        }
    }
    int g = lane >> 2, tq = lane & 3;
    uint32_t* py = g_yh + (size_t)blc*SW_;
    #pragma unroll
    for (int nt = 0; nt < 16; nt++) {
        int w = (nh*16 + nt)*4 + tq;
        __half2 h1 = __floats2half2_rn(acc[nt][0], acc[nt][1]);
        __half2 h2 = __floats2half2_rn(acc[nt][2], acc[nt][3]);
        py[(mrow + g)*W_ + w]     = *(uint32_t*)&h1;
        py[(mrow + g + 8)*W_ + w] = *(uint32_t*)&h2;
    }
}

// ---------------- K8: fp16 mma.sync conv-GEMM, 4 s-rows per CTA ----------------
#define CONV_SMEM (199680 + 16384)
__global__ void __launch_bounds__(512) k_conv_mma() {
    extern __shared__ __align__(16) char smc[];
    char* sB = smc + 199680;
    int tid = threadIdx.x, lane = tid & 31, warp = tid >> 5;
    int bl = blockIdx.x >> 4, s0 = (blockIdx.x & 15) * 4;

    const uint32_t* ybl = g_yh + (size_t)bl * (C_*SW_);
    for (int i = tid; i < 6*130*64; i += 512) {
        int ci = i / 780, rem = i % 780;
        int ds = rem / 130, pw = rem % 130;
        int sr = s0 + ds - 1, w = pw - 1;
        uint32_t v = 0u;
        if (((unsigned)sr < (unsigned)S_) && ((unsigned)w < (unsigned)W_))
            v = ybl[(size_t)ci*SW_ + sr*W_ + w];
        int phys = ds*33280 + pw*256 + ((((ci >> 2) ^ (pw & 7))) << 4) + (ci & 3)*4;
        *(uint32_t*)(smc + phys) = v;
    }

    float acc[2][8][4];
    #pragma unroll
    for (int mt = 0; mt < 2; mt++)
        #pragma unroll
        for (int nt = 0; nt < 8; nt++)
            #pragma unroll
            for (int j = 0; j < 4; j++) acc[mt][nt][j] = 0.f;

    uint32_t sAu = smem_u32(smc), sBu = smem_u32(sB);
    int s_row = warp >> 2;
    int wbase = (warp & 3) * 32;

    #pragma unroll 1
    for (int t = 0; t < 9; t++) {
        __syncthreads();
        {
            const uint4* src = (const uint4*)(g_Bw + t*8192);
            uint4* dst = (uint4*)sB;
            dst[tid]       = src[tid];
            dst[tid + 512] = src[tid + 512];
        }
        __syncthreads();
        int tx = t % 3, ds = s_row + t / 3;
        #pragma unroll 1
        for (int ks = 0; ks < 8; ks++) {
            uint32_t a0[2], a1[2], a2[2], a3[2];
            #pragma unroll
            for (int mt = 0; mt < 2; mt++) {
                int row = wbase + mt*16 + (lane & 15) + tx;
                int cblk = ks*2 + (lane >> 4);
                uint32_t aaddr = sAu + ds*33280 + row*256 + (uint32_t)((cblk ^ (row & 7)) << 4);
                asm volatile("ldmatrix.sync.aligned.m8n8.x4.shared.b16 {%0,%1,%2,%3}, [%4];"
                             : "=r"(a0[mt]), "=r"(a1[mt]), "=r"(a2[mt]), "=r"(a3[mt]) : "r"(aaddr));
            }
            #pragma unroll
            for (int np = 0; np < 4; np++) {
                int n = (np*2 + (lane >> 4))*8 + (lane & 7);
                int cb = ks*2 + ((lane >> 3) & 1);
                uint32_t baddr = sBu + n*256 + (uint32_t)((cb ^ (n & 7)) << 4);
                uint32_t b0, b1, b2, b3;
                asm volatile("ldmatrix.sync.aligned.m8n8.x4.shared.b16 {%0,%1,%2,%3}, [%4];"
                             : "=r"(b0), "=r"(b1), "=r"(b2), "=r"(b3) : "r"(baddr));
                #pragma unroll
                for (int mt = 0; mt < 2; mt++) {
                    asm volatile("mma.sync.aligned.m16n8k16.row.col.f32.f16.f16.f32 "
                                 "{%0,%1,%2,%3}, {%4,%5,%6,%7}, {%8,%9}, {%0,%1,%2,%3};"
                                 : "+f"(acc[mt][np*2][0]), "+f"(acc[mt][np*2][1]),
                                   "+f"(acc[mt][np*2][2]), "+f"(acc[mt][np*2][3])
                                 : "r"(a0[mt]), "r"(a1[mt]), "r"(a2[mt]), "r"(a3[mt]),
                                   "r"(b0), "r"(b1));
                    asm volatile("mma.sync.aligned.m16n8k16.row.col.f32.f16.f16.f32 "
                                 "{%0,%1,%2,%3}, {%4,%5,%6,%7}, {%8,%9}, {%0,%1,%2,%3};"
                                 : "+f"(acc[mt][np*2+1][0]), "+f"(acc[mt][np*2+1][1]),
                                   "+f"(acc[mt][np*2+1][2]), "+f"(acc[mt][np*2+1][3])
                                 : "r"(a0[mt]), "r"(a1[mt]), "r"(a2[mt]), "r"(a3[mt]),
                                   "r"(b2), "r"(b3));
                }
            }
        }
    }
    int g = lane >> 2, tq = lane & 3;
    #pragma unroll
    for (int mt = 0; mt < 2; mt++) {
        uint32_t* ob = g_fh + (size_t)bl * (32*SW_) + (s0 + s_row)*W_ + wbase + mt*16 + g;
        #pragma unroll
        for (int nt = 0; nt < 8; nt++) {
            int pi = nt*4 + tq;
            __half2 hA = __floats2half2_rn(acc[mt][nt][0], acc[mt][nt][1]);
            __half2 hB = __floats2half2_rn(acc[mt][nt][2], acc[mt][nt][3]);
            ob[(size_t)pi*SW_]     = *(uint32_t*)&hA;
            ob[(size_t)pi*SW_ + 8] = *(uint32_t*)&hB;
        }
    }
}

// ---------------- K9: LayerNorm over o-pairs (+ bias) + residual ----------------
__global__ void __launch_bounds__(512) k_ln(const float* __restrict__ x,
                     const float* __restrict__ lng,
                     const float* __restrict__ lnb, float* __restrict__ out) {
    __shared__ float sbuf1[16], sbuf2[16];
    __shared__ float s_mu0, s_r0, s_mu1, s_r1;
    int blc2 = blockIdx.x, tid = threadIdx.x;
    int bl = blc2 >> 5, op = blc2 & 31;
    int o0 = op * 2;
    const uint32_t* fp = g_fh + (size_t)blc2 * SW_;
    const float* bp0 = g_bias + (size_t)o0 * SW_;
    const float* bp1 = g_bias + (size_t)(o0 + 1) * SW_;
    float v0[16], v1[16];
    float sum0 = 0.f, sq0 = 0.f, sum1 = 0.f, sq1 = 0.f;
    #pragma unroll
    for (int k = 0; k < 16; k++) {
        int i = tid + 512*k;
        uint32_t u = fp[i];
        __half2 h = *(__half2*)&u;
        float2 f = __half22float2(h);
        float t0 = f.x + bp0[i];
        float t1 = f.y + bp1[i];
        v0[k] = t0; v1[k] = t1;
        sum0 += t0; sq0 += t0*t0;
        sum1 += t1; sq1 += t1*t1;
    }
    float ts0 = blockReduceSum(sum0, sbuf1);
    __syncthreads();
    float tq0 = blockReduceSum(sq0, sbuf2);
    __syncthreads();
    float ts1 = blockReduceSum(sum1, sbuf1);
    __syncthreads();
    float tq1 = blockReduceSum(sq1, sbuf2);
    if (tid == 0) {
        float mu0 = ts0 * (1.f / (float)SW_);
        float var0 = tq0 * (1.f / (float)SW_) - mu0*mu0;
        s_mu0 = mu0; s_r0 = rsqrtf(var0 + 1e-5f);
        float mu1 = ts1 * (1.f / (float)SW_);
        float var1 = tq1 * (1.f / (float)SW_) - mu1*mu1;
        s_mu1 = mu1; s_r1 = rsqrtf(var1 + 1e-5f);
    }
    __syncthreads();
    float mu0 = s_mu0, r0 = s_r0, mu1 = s_mu1, r1 = s_r1;
    const float* xp0 = x + ((size_t)bl*C_ + o0)*SW_;
    const float* xp1 = xp0 + SW_;
    float* op0 = out + ((size_t)bl*C_ + o0)*SW_;
    float* op1 = op0 + SW_;
    #pragma unroll
    for (int k = 0; k < 16; k++) {
        int i = tid + 512*k;
        float gg = lng[i], bb = lnb[i];
        op0[i] = (v0[k] - mu0) * r0 * gg + bb + xp0[i];
        op1[i] = (v1[k] - mu1) * r1 * gg + bb + xp1[i];
    }
}

// ---------------- launch ----------------
extern "C" void kernel_launch(void* const* d_in, const int* in_sizes, int n_in,
                              void* d_out, int out_size) {
    const float* x         = (const float*)d_in[0];
    const float* nu_log    = (const float*)d_in[1];
    const float* theta_log = (const float*)d_in[2];
    const float* disp_nu   = (const float*)d_in[3];
    const float* disp_th   = (const float*)d_in[4];
    const float* mlp_w1    = (const float*)d_in[5];
    const float* mlp_b1    = (const float*)d_in[6];
    const float* mlp_w2    = (const float*)d_in[7];
    const float* mlp_b2    = (const float*)d_in[8];
    const float* fscale    = (const float*)d_in[9];
    const float* U_row_r   = (const float*)d_in[10];
    const float* U_row_i   = (const float*)d_in[11];
    const float* V_col_r   = (const float*)d_in[12];
    const float* V_col_i   = (const float*)d_in[13];
    const float* proj_W_r  = (const float*)d_in[14];
    const float* proj_W_i  = (const float*)d_in[15];
    const float* proj_b_r  = (const float*)d_in[16];
    const float* proj_b_i  = (const float*)d_in[17];
    const float* convr_k   = (const float*)d_in[18];
    const float* convr_b   = (const float*)d_in[19];
    const float* convi_k   = (const float*)d_in[20];
    const float* convi_b   = (const float*)d_in[21];
    const float* fuse_k    = (const float*)d_in[22];
    const float* fuse_b    = (const float*)d_in[23];
    const float* ln_g      = (const float*)d_in[24];
    const float* ln_b      = (const float*)d_in[25];
    float* out = (float*)d_out;

    cudaFuncSetAttribute(k_u_prep,   cudaFuncAttributeMaxDynamicSharedMemorySize, SMEM_U_BYTES);
    cudaFuncSetAttribute(k_conv_mma, cudaFuncAttributeMaxDynamicSharedMemorySize, CONV_SMEM);

    k_u_prep<<<2112, 256, SMEM_U_BYTES>>>(x, U_row_r, U_row_i, V_col_r, V_col_i,
                                          fuse_k, convr_k, convi_k, convr_b, convi_b, fuse_b,
                                          proj_W_r, proj_W_i, proj_b_r, proj_b_i);
    k_scan<<<16, 256>>>(nu_log, theta_log, disp_nu, disp_th,
                        mlp_w1, mlp_b1, mlp_w2, mlp_b2, fscale);
    k_recon_mma<<<PLANES_, 256>>>(U_row_r, U_row_i, V_col_r, V_col_i);
    k_conv_mma<<<512, 512, CONV_SMEM>>>();
    k_ln<<<1024, 512>>>(x, ln_g, ln_b, out);
}